// round 1
// baseline (speedup 1.0000x reference)
#include <cuda_runtime.h>
#include <cstdint>

// ---------------------------------------------------------------------------
// Problem constants (fixed shapes)
// ---------------------------------------------------------------------------
#define BATCH     8
#define KPTS      4096
#define NPTS      (BATCH * KPTS)      // 32768
#define DM        192
#define DIN       800
#define NFREQ     8
#define PEW       (4 * NFREQ)         // 32
#define PIX_PB    21760               // 16384 + 4096 + 1024 + 256 per batch

// per-level tables
__device__ __constant__ int c_HW[4]   = {16384, 4096, 1024, 256};
__device__ __constant__ int c_W[4]    = {128, 64, 32, 16};
__device__ __constant__ int c_LOFF[4] = {0, 16384, 20480, 21504};

// ---------------------------------------------------------------------------
// Static device scratch (no runtime allocation allowed)
// ---------------------------------------------------------------------------
__device__ float g_P[(size_t)BATCH * PIX_PB * DM];   // projected maps, channel-last (~134 MB)
__device__ float g_PE[(size_t)NPTS * PEW];           // fourier PE matrix  (4 MB)
__device__ float g_peW[(size_t)NPTS * DM];           // PE @ Wseed_pe^T    (25 MB)
__device__ float g_Wt[DIN * DM];                     // Wseed transposed [c][d]
__device__ float g_WposT[PEW * DM];                  // Wpos transposed [j][d]

// ---------------------------------------------------------------------------
// packed f32x2 helpers (FFMA2 — 2x fp32 FMA throughput on sm_103a)
// ---------------------------------------------------------------------------
__device__ __forceinline__ unsigned long long pack2(float lo, float hi) {
    unsigned long long r;
    asm("mov.b64 %0, {%1,%2};" : "=l"(r) : "f"(lo), "f"(hi));
    return r;
}
__device__ __forceinline__ void unpack2(unsigned long long v, float& lo, float& hi) {
    asm("mov.b64 {%0,%1}, %2;" : "=f"(lo), "=f"(hi) : "l"(v));
}
__device__ __forceinline__ void ffma2(unsigned long long& d, unsigned long long a,
                                      unsigned long long b, unsigned long long c) {
    asm("fma.rn.f32x2 %0, %1, %2, %3;" : "=l"(d) : "l"(a), "l"(b), "l"(c));
}

// shared microkernel step: 4 m-values (float4) x 12 n-values (6 packed pairs)
__device__ __forceinline__ void mk_step(float4 xv, const float* wrow,
                                        unsigned long long acc[4][6]) {
    const ulonglong2* wp = (const ulonglong2*)wrow;
    ulonglong2 wa = wp[0], wb = wp[1], wc = wp[2];
    unsigned long long w[6] = {wa.x, wa.y, wb.x, wb.y, wc.x, wc.y};
    unsigned long long xp[4] = {pack2(xv.x, xv.x), pack2(xv.y, xv.y),
                                pack2(xv.z, xv.z), pack2(xv.w, xv.w)};
#pragma unroll
    for (int m = 0; m < 4; m++)
#pragma unroll
        for (int q = 0; q < 6; q++)
            ffma2(acc[m][q], xp[m], w[q], acc[m][q]);
}

// ---------------------------------------------------------------------------
// Kernel 1: transpose the weight matrices into scratch
// ---------------------------------------------------------------------------
__global__ void __launch_bounds__(256) k_prep(const float* __restrict__ Wseed_w,
                                              const float* __restrict__ Wpos_w) {
    int idx = blockIdx.x * 256 + threadIdx.x;
    if (idx < DIN * DM) {
        int c = idx / DM, d = idx % DM;
        g_Wt[idx] = Wseed_w[(size_t)d * DIN + c];
    } else if (idx < DIN * DM + PEW * DM) {
        int i2 = idx - DIN * DM;
        int j = i2 / DM, d = i2 % DM;
        g_WposT[i2] = Wpos_w[(size_t)d * PEW + j];
    }
}

// ---------------------------------------------------------------------------
// Kernel 2: Fourier PE matrix + center_grid output
// one thread per (point, j)
// ---------------------------------------------------------------------------
__global__ void __launch_bounds__(256) k_pe(const float* __restrict__ coords,
                                            float* __restrict__ out_cg) {
    int gid = blockIdx.x * 256 + threadIdx.x;
    int p = gid >> 5;
    int j = gid & 31;
    if (p >= NPTS) return;
    float cx = coords[(size_t)p * 2 + 0];
    float cy = coords[(size_t)p * 2 + 1];
    int grp = j >> 3;
    float f = (float)(1 << (j & 7));
    float cn = ((grp < 2) ? cx : cy) * (1.0f / 512.0f);
    float arg = (cn * f) * 6.283185307179586f;
    float val = (grp & 1) ? cosf(arg) : sinf(arg);
    g_PE[(size_t)p * PEW + j] = val;
    if (j == 0) {
        out_cg[(size_t)p * 2 + 0] = 2.0f * cx / 511.0f - 1.0f;
        out_cg[(size_t)p * 2 + 1] = 2.0f * cy / 511.0f - 1.0f;
    }
}

// ---------------------------------------------------------------------------
// Kernel 3: per-level projection GEMM, fp32 (packed f32x2), channel-last out
//   P[b][pix][d] = sum_c F_l[b][c][pix] * Wseed[d][l*192+c]
// tiles: Mt=64 pixels, Nt=192 (full), Kt=32. 256 threads, thread tile 4x12.
// ---------------------------------------------------------------------------
__global__ void __launch_bounds__(256) k_proj(const float* __restrict__ F0,
                                              const float* __restrict__ F1,
                                              const float* __restrict__ F2,
                                              const float* __restrict__ F3) {
    __shared__ float Fs[32][64];
    __shared__ float Ws[32][192];

    int t = blockIdx.x, b = blockIdx.y;
    int l, mt;
    if (t < 256)      { l = 0; mt = t; }
    else if (t < 320) { l = 1; mt = t - 256; }
    else if (t < 336) { l = 2; mt = t - 320; }
    else              { l = 3; mt = t - 336; }
    const int HW = c_HW[l];
    const int LO = c_LOFF[l];
    const float* F = (l == 0) ? F0 : (l == 1) ? F1 : (l == 2) ? F2 : F3;
    F += (size_t)b * DM * HW;
    const int p0 = mt * 64;

    const int tid = threadIdx.x;
    const int tx = tid & 15, ty = tid >> 4;

    unsigned long long acc[4][6];
#pragma unroll
    for (int m = 0; m < 4; m++)
#pragma unroll
        for (int q = 0; q < 6; q++) acc[m][q] = 0ULL;

    for (int kt = 0; kt < 6; kt++) {
        const int c0 = kt * 32;
        // load F tile (k-major already: F[c][p]) — coalesced float4 along p
#pragma unroll
        for (int i = 0; i < 2; i++) {
            int idx = tid + 256 * i;            // < 512
            int kc = idx >> 4, m4 = idx & 15;
            *(float4*)&Fs[kc][m4 * 4] =
                *(const float4*)(F + (size_t)(c0 + kc) * HW + p0 + m4 * 4);
        }
        // load W tile (already transposed): rows l*192+c0..+31, 192 wide
#pragma unroll
        for (int i = 0; i < 6; i++) {
            int idx = tid + 256 * i;            // < 1536
            int kc = idx / 48, d4 = idx % 48;
            *(float4*)&Ws[kc][d4 * 4] =
                *(const float4*)(g_Wt + (size_t)(l * DM + c0 + kc) * DM + d4 * 4);
        }
        __syncthreads();
#pragma unroll 8
        for (int kc = 0; kc < 32; kc++) {
            float4 xv = *(const float4*)&Fs[kc][ty * 4];
            mk_step(xv, &Ws[kc][tx * 12], acc);
        }
        __syncthreads();
    }

    size_t obase = ((size_t)b * PIX_PB + LO + p0 + ty * 4) * DM + tx * 12;
#pragma unroll
    for (int m = 0; m < 4; m++) {
        float o[12];
#pragma unroll
        for (int q = 0; q < 6; q++) unpack2(acc[m][q], o[2 * q], o[2 * q + 1]);
        float* dst = g_P + obase + (size_t)m * DM;
        *(float4*)(dst + 0) = make_float4(o[0], o[1], o[2], o[3]);
        *(float4*)(dst + 4) = make_float4(o[4], o[5], o[6], o[7]);
        *(float4*)(dst + 8) = make_float4(o[8], o[9], o[10], o[11]);
    }
}

// ---------------------------------------------------------------------------
// Kernel 4: PE GEMMs.  z=0: g_peW = PE @ Wseed_pe^T ;  z=1: pos = PE @ Wpos^T + b
//   M=32768, K=32, N=192. Mt=64, single K tile.
// ---------------------------------------------------------------------------
__global__ void __launch_bounds__(256) k_pegemm(const float* __restrict__ Wpos_b,
                                                float* __restrict__ out_pos) {
    __shared__ float Fs[32][68];   // [k][m], padded
    __shared__ float Ws[32][192];

    const int z = blockIdx.y;
    const int p0 = blockIdx.x * 64;
    const int tid = threadIdx.x;
    const int tx = tid & 15, ty = tid >> 4;

    // load PE tile, transposing m-major -> k-major in smem
#pragma unroll
    for (int i = 0; i < 8; i++) {
        int idx = tid + 256 * i;               // < 2048
        int m = idx >> 5, j = idx & 31;
        Fs[j][m] = g_PE[(size_t)(p0 + m) * PEW + j];
    }
    const float* Wsrc = z ? g_WposT : (g_Wt + 768 * DM);
    float* wsf = &Ws[0][0];
#pragma unroll
    for (int i = 0; i < 24; i++) {
        int idx = tid + 256 * i;               // < 6144
        wsf[idx] = Wsrc[idx];
    }
    __syncthreads();

    unsigned long long acc[4][6];
#pragma unroll
    for (int m = 0; m < 4; m++)
#pragma unroll
        for (int q = 0; q < 6; q++) acc[m][q] = 0ULL;

#pragma unroll 8
    for (int kc = 0; kc < 32; kc++) {
        float4 xv = *(const float4*)&Fs[kc][ty * 4];
        mk_step(xv, &Ws[kc][tx * 12], acc);
    }

#pragma unroll
    for (int m = 0; m < 4; m++) {
        float o[12];
#pragma unroll
        for (int q = 0; q < 6; q++) unpack2(acc[m][q], o[2 * q], o[2 * q + 1]);
        size_t row = (size_t)(p0 + ty * 4 + m) * DM + tx * 12;
        if (z == 0) {
            float* dst = g_peW + row;
            *(float4*)(dst + 0) = make_float4(o[0], o[1], o[2], o[3]);
            *(float4*)(dst + 4) = make_float4(o[4], o[5], o[6], o[7]);
            *(float4*)(dst + 8) = make_float4(o[8], o[9], o[10], o[11]);
        } else {
#pragma unroll
            for (int q = 0; q < 12; q++) o[q] += Wpos_b[tx * 12 + q];
            float* dst = out_pos + row;
            *(float4*)(dst + 0) = make_float4(o[0], o[1], o[2], o[3]);
            *(float4*)(dst + 4) = make_float4(o[4], o[5], o[6], o[7]);
            *(float4*)(dst + 8) = make_float4(o[8], o[9], o[10], o[11]);
        }
    }
}

// ---------------------------------------------------------------------------
// Kernel 5: gather + bilinear combine + LayerNorm.  1 warp = 1 point.
// ---------------------------------------------------------------------------
__global__ void __launch_bounds__(256) k_gather(const float* __restrict__ coords,
                                                const float* __restrict__ seed_b,
                                                const float* __restrict__ lng,
                                                const float* __restrict__ lnb,
                                                float* __restrict__ out_seed) {
    const int b = blockIdx.y;
    const int wid = threadIdx.x >> 5;
    const int lane = threadIdx.x & 31;
    const int k = blockIdx.x * 8 + wid;
    const int gp = b * KPTS + k;

    const float cx = coords[(size_t)gp * 2 + 0];
    const float cy = coords[(size_t)gp * 2 + 1];
    const float gx = 2.0f * cx / 511.0f - 1.0f;
    const float gy = 2.0f * cy / 511.0f - 1.0f;

    float acc[6];
#pragma unroll
    for (int r = 0; r < 6; r++) {
        int d = r * 32 + lane;
        acc[r] = seed_b[d] + g_peW[(size_t)gp * DM + d];
    }

#pragma unroll
    for (int l = 0; l < 4; l++) {
        const int W = c_W[l];
        const float ix = (gx + 1.0f) * 0.5f * (float)(W - 1);
        const float iy = (gy + 1.0f) * 0.5f * (float)(W - 1);
        const float fx0 = floorf(ix);
        const float fy0 = floorf(iy);
        const float wx = ix - fx0;
        const float wy = iy - fy0;
        int x0 = min(max((int)fx0, 0), W - 1);
        int x1 = min(max((int)fx0 + 1, 0), W - 1);
        int y0 = min(max((int)fy0, 0), W - 1);
        int y1 = min(max((int)fy0 + 1, 0), W - 1);
        const float w00 = (1.0f - wx) * (1.0f - wy);
        const float w01 = wx * (1.0f - wy);
        const float w10 = (1.0f - wx) * wy;
        const float w11 = wx * wy;
        const size_t base = ((size_t)b * PIX_PB + c_LOFF[l]) * DM;
        const float* p00 = g_P + base + (size_t)(y0 * W + x0) * DM;
        const float* p01 = g_P + base + (size_t)(y0 * W + x1) * DM;
        const float* p10 = g_P + base + (size_t)(y1 * W + x0) * DM;
        const float* p11 = g_P + base + (size_t)(y1 * W + x1) * DM;
#pragma unroll
        for (int r = 0; r < 6; r++) {
            int d = r * 32 + lane;
            acc[r] += w00 * __ldg(p00 + d) + w01 * __ldg(p01 + d)
                    + w10 * __ldg(p10 + d) + w11 * __ldg(p11 + d);
        }
    }

    // LayerNorm over 192 values (6 per lane) via warp reduction
    float s = 0.0f, s2 = 0.0f;
#pragma unroll
    for (int r = 0; r < 6; r++) { s += acc[r]; s2 += acc[r] * acc[r]; }
#pragma unroll
    for (int o = 16; o > 0; o >>= 1) {
        s  += __shfl_xor_sync(0xFFFFFFFFu, s, o);
        s2 += __shfl_xor_sync(0xFFFFFFFFu, s2, o);
    }
    const float mu = s * (1.0f / 192.0f);
    const float var = s2 * (1.0f / 192.0f) - mu * mu;
    const float inv = rsqrtf(var + 1e-5f);

    float* dst = out_seed + (size_t)gp * DM;
#pragma unroll
    for (int r = 0; r < 6; r++) {
        int d = r * 32 + lane;
        dst[d] = (acc[r] - mu) * inv * lng[d] + lnb[d];
    }
}

// ---------------------------------------------------------------------------
// launch
// ---------------------------------------------------------------------------
extern "C" void kernel_launch(void* const* d_in, const int* in_sizes, int n_in,
                              void* d_out, int out_size) {
    const float* coords  = (const float*)d_in[0];
    const float* L1      = (const float*)d_in[1];
    const float* L2      = (const float*)d_in[2];
    const float* L3      = (const float*)d_in[3];
    const float* L4      = (const float*)d_in[4];
    const float* Wseed_w = (const float*)d_in[5];
    const float* Wseed_b = (const float*)d_in[6];
    const float* ln_g    = (const float*)d_in[7];
    const float* ln_b    = (const float*)d_in[8];
    const float* Wpos_w  = (const float*)d_in[9];
    const float* Wpos_b  = (const float*)d_in[10];

    float* out      = (float*)d_out;
    float* out_seed = out;
    float* out_pos  = out + (size_t)NPTS * DM;
    float* out_cg   = out + (size_t)2 * NPTS * DM;

    k_prep<<<(DIN * DM + PEW * DM + 255) / 256, 256>>>(Wseed_w, Wpos_w);
    k_pe<<<(NPTS * PEW) / 256, 256>>>(coords, out_cg);
    k_proj<<<dim3(340, BATCH), 256>>>(L1, L2, L3, L4);
    k_pegemm<<<dim3(NPTS / 64, 2), 256>>>(Wpos_b, out_pos);
    k_gather<<<dim3(KPTS / 8, BATCH), 256>>>(coords, Wseed_b, ln_g, ln_b, out_seed);
}

// round 3
// speedup vs baseline: 1.6366x; 1.6366x over previous
#include <cuda_runtime.h>
#include <cuda_bf16.h>
#include <cstdint>

// ---------------------------------------------------------------------------
// Problem constants
// ---------------------------------------------------------------------------
#define BATCH     8
#define KPTS      4096
#define NPTS      (BATCH * KPTS)      // 32768
#define DM        192
#define DIN       800
#define PEW       32
#define PIX_PB    21760               // 16384+4096+1024+256
#define TPB64     340                 // 64-px tiles per batch

__device__ __constant__ int c_HW[4]    = {16384, 4096, 1024, 256};
__device__ __constant__ int c_Wd[4]    = {128, 64, 32, 16};
__device__ __constant__ int c_LOFF[4]  = {0, 16384, 20480, 21504};

// ---------------------------------------------------------------------------
// Static device scratch
// ---------------------------------------------------------------------------
__device__ float g_P[(size_t)BATCH * PIX_PB * DM];    // projected maps [pix][d]
__device__ float g_PE[(size_t)NPTS * PEW];
__device__ float g_peW[(size_t)NPTS * DM];
__device__ float g_Wt[DIN * DM];
__device__ float g_WposT[PEW * DM];
__device__ __nv_bfloat16 g_Wbf[2][4][DM][DM];         // [hi/lo][level][d][c]

// ---------------------------------------------------------------------------
// HMMA helpers (generic sm_80+ PTX — works on compute_103 target)
// ---------------------------------------------------------------------------
__device__ __forceinline__ uint32_t smem_u32(const void* p) {
    uint32_t a;
    asm("{ .reg .u64 t; cvta.to.shared.u64 t, %1; cvt.u32.u64 %0, t; }" : "=r"(a) : "l"(p));
    return a;
}
__device__ __forceinline__ void ldmx4(uint32_t r[4], uint32_t addr) {
    asm volatile("ldmatrix.sync.aligned.m8n8.x4.shared.b16 {%0,%1,%2,%3}, [%4];"
                 : "=r"(r[0]), "=r"(r[1]), "=r"(r[2]), "=r"(r[3]) : "r"(addr));
}
__device__ __forceinline__ void mma_bf16(float c[4], const uint32_t a[4],
                                         uint32_t b0, uint32_t b1) {
    asm volatile("mma.sync.aligned.m16n8k16.row.col.f32.bf16.bf16.f32 "
                 "{%0,%1,%2,%3}, {%4,%5,%6,%7}, {%8,%9}, {%0,%1,%2,%3};"
                 : "+f"(c[0]), "+f"(c[1]), "+f"(c[2]), "+f"(c[3])
                 : "r"(a[0]), "r"(a[1]), "r"(a[2]), "r"(a[3]), "r"(b0), "r"(b1));
}

// ---------------------------------------------------------------------------
// packed f32x2 helpers (pegemm)
// ---------------------------------------------------------------------------
__device__ __forceinline__ unsigned long long pack2(float lo, float hi) {
    unsigned long long r;
    asm("mov.b64 %0, {%1,%2};" : "=l"(r) : "f"(lo), "f"(hi));
    return r;
}
__device__ __forceinline__ void unpack2(unsigned long long v, float& lo, float& hi) {
    asm("mov.b64 {%0,%1}, %2;" : "=f"(lo), "=f"(hi) : "l"(v));
}
__device__ __forceinline__ void ffma2(unsigned long long& d, unsigned long long a,
                                      unsigned long long b, unsigned long long c) {
    asm("fma.rn.f32x2 %0, %1, %2, %3;" : "=l"(d) : "l"(a), "l"(b), "l"(c));
}
__device__ __forceinline__ void mk_step(float4 xv, const float* wrow,
                                        unsigned long long acc[4][6]) {
    const ulonglong2* wp = (const ulonglong2*)wrow;
    ulonglong2 wa = wp[0], wb = wp[1], wc = wp[2];
    unsigned long long w[6] = {wa.x, wa.y, wb.x, wb.y, wc.x, wc.y};
    unsigned long long xp[4] = {pack2(xv.x, xv.x), pack2(xv.y, xv.y),
                                pack2(xv.z, xv.z), pack2(xv.w, xv.w)};
#pragma unroll
    for (int m = 0; m < 4; m++)
#pragma unroll
        for (int q = 0; q < 6; q++)
            ffma2(acc[m][q], xp[m], w[q], acc[m][q]);
}

// ---------------------------------------------------------------------------
// Kernel 1: weight prep (transposes + bf16 hi/lo split of Wseed feature part)
// ---------------------------------------------------------------------------
__global__ void __launch_bounds__(256) k_prep(const float* __restrict__ Wseed_w,
                                              const float* __restrict__ Wpos_w) {
    int idx = blockIdx.x * 256 + threadIdx.x;
    if (idx < DIN * DM) {
        int c = idx / DM, d = idx % DM;
        g_Wt[idx] = Wseed_w[(size_t)d * DIN + c];
    } else if (idx < DIN * DM + PEW * DM) {
        int i2 = idx - DIN * DM;
        int j = i2 / DM, d = i2 % DM;
        g_WposT[i2] = Wpos_w[(size_t)d * PEW + j];
    } else if (idx < DIN * DM + PEW * DM + 4 * DM * DM) {
        int i3 = idx - DIN * DM - PEW * DM;
        int l = i3 / (DM * DM);
        int d = (i3 % (DM * DM)) / DM;
        int c = i3 % DM;
        float w = Wseed_w[(size_t)d * DIN + l * DM + c];
        __nv_bfloat16 h = __float2bfloat16(w);
        __nv_bfloat16 lo = __float2bfloat16(w - __bfloat162float(h));
        g_Wbf[0][l][d][c] = h;
        g_Wbf[1][l][d][c] = lo;
    }
}

// ---------------------------------------------------------------------------
// Kernel 2: Fourier PE + center_grid
// ---------------------------------------------------------------------------
__global__ void __launch_bounds__(256) k_pe(const float* __restrict__ coords,
                                            float* __restrict__ out_cg) {
    int gid = blockIdx.x * 256 + threadIdx.x;
    int p = gid >> 5;
    int j = gid & 31;
    if (p >= NPTS) return;
    float cx = coords[(size_t)p * 2 + 0];
    float cy = coords[(size_t)p * 2 + 1];
    int grp = j >> 3;
    float f = (float)(1 << (j & 7));
    float cn = ((grp < 2) ? cx : cy) * (1.0f / 512.0f);
    float arg = (cn * f) * 6.283185307179586f;
    float val = (grp & 1) ? cosf(arg) : sinf(arg);
    g_PE[(size_t)p * PEW + j] = val;
    if (j == 0) {
        out_cg[(size_t)p * 2 + 0] = 2.0f * cx / 511.0f - 1.0f;
        out_cg[(size_t)p * 2 + 1] = 2.0f * cy / 511.0f - 1.0f;
    }
}

// ---------------------------------------------------------------------------
// Kernel 3: HMMA bf16 3-split projection GEMM with fused transpose/convert
//   P[pix][d] = sum_c F[c][pix] * Wl[d][c]   (per level)
// CTA: 64 px x 192 d, 8 warps (2m x 4n), K=192 in 3 chunks of 64.
// SMEM (dynamic, 90880B):
//   Bs_h [192][72] bf16 @0      Bs_l @27648
//   As_h [64][72]  bf16 @55296  As_l @64512
//   Fs   [64][67]  f32  @73728
// ---------------------------------------------------------------------------
#define SM_BSH 0
#define SM_BSL 27648
#define SM_ASH 55296
#define SM_ASL 64512
#define SM_FS  73728
#define SMEM_G 90880

__global__ void __launch_bounds__(256, 2) k_gemm(const float* __restrict__ F0,
                                                 const float* __restrict__ F1,
                                                 const float* __restrict__ F2,
                                                 const float* __restrict__ F3) {
    extern __shared__ char smem[];
    __nv_bfloat16* Bs_h = (__nv_bfloat16*)(smem + SM_BSH);
    __nv_bfloat16* Bs_l = (__nv_bfloat16*)(smem + SM_BSL);
    __nv_bfloat16* As_h = (__nv_bfloat16*)(smem + SM_ASH);
    __nv_bfloat16* As_l = (__nv_bfloat16*)(smem + SM_ASL);
    float*         Fs   = (float*)(smem + SM_FS);
    const uint32_t u_ash = smem_u32(As_h), u_asl = smem_u32(As_l);
    const uint32_t u_bsh = smem_u32(Bs_h), u_bsl = smem_u32(Bs_l);

    const int tid = threadIdx.x;
    const int lane = tid & 31, wid = tid >> 5;
    const int warp_m = wid & 1, warp_n = wid >> 1;

    const int b = blockIdx.x / TPB64;
    const int r = blockIdx.x % TPB64;
    int level, tin;
    if (r < 256)      { level = 0; tin = r; }
    else if (r < 320) { level = 1; tin = r - 256; }
    else if (r < 336) { level = 2; tin = r - 320; }
    else              { level = 3; tin = r - 336; }
    const int HW = c_HW[level];
    const float* F = (level == 0) ? F0 : (level == 1) ? F1 : (level == 2) ? F2 : F3;
    F += (size_t)b * DM * HW + tin * 64;
    const __nv_bfloat16* Wh = &g_Wbf[0][level][0][0];
    const __nv_bfloat16* Wl = &g_Wbf[1][level][0][0];

    float acc[2][6][4];
#pragma unroll
    for (int mi = 0; mi < 2; mi++)
#pragma unroll
        for (int n8 = 0; n8 < 6; n8++)
#pragma unroll
            for (int e = 0; e < 4; e++) acc[mi][n8][e] = 0.0f;

    // ldmatrix lane address components
    const int arow = lane & 15;
    const int acol8 = (lane >> 4) << 3;
    const int brow = (lane & 7) + ((lane >> 4) << 3);
    const int bcol8 = ((lane >> 3) & 1) << 3;
    const int px_cv = tid >> 2;           // convert phase: pixel
    const int q_cv = tid & 3;             // convert phase: c-quarter

    for (int cz = 0; cz < 3; cz++) {
        const int c0 = cz * 64;
        // ---- load B chunk (hi+lo), rows [192][64] ----
#pragma unroll
        for (int i = tid; i < 1536; i += 256) {
            int d = i >> 3, u = i & 7;
            *(uint4*)(Bs_h + d * 72 + u * 8) = *(const uint4*)(Wh + d * DM + c0 + u * 8);
            *(uint4*)(Bs_l + d * 72 + u * 8) = *(const uint4*)(Wl + d * DM + c0 + u * 8);
        }
        // ---- stage F chunk [64c][64px] fp32 ----
#pragma unroll
        for (int i = tid; i < 1024; i += 256) {
            int c = i >> 4, p4 = (i & 15) << 2;
            float4 v = *(const float4*)(F + (size_t)(c0 + c) * HW + p4);
            Fs[c * 67 + p4 + 0] = v.x; Fs[c * 67 + p4 + 1] = v.y;
            Fs[c * 67 + p4 + 2] = v.z; Fs[c * 67 + p4 + 3] = v.w;
        }
        __syncthreads();
        // ---- transpose + convert to bf16 hi/lo: As[px][c] ----
#pragma unroll
        for (int g = 0; g < 2; g++) {
            union { unsigned short s[8]; uint4 v; } uh, ul;
#pragma unroll
            for (int e = 0; e < 8; e++) {
                int c = q_cv * 16 + g * 8 + e;
                float v = Fs[c * 67 + px_cv];
                __nv_bfloat16 h = __float2bfloat16(v);
                __nv_bfloat16 lo = __float2bfloat16(v - __bfloat162float(h));
                uh.s[e] = *(unsigned short*)&h;
                ul.s[e] = *(unsigned short*)&lo;
            }
            *(uint4*)(As_h + px_cv * 72 + q_cv * 16 + g * 8) = uh.v;
            *(uint4*)(As_l + px_cv * 72 + q_cv * 16 + g * 8) = ul.v;
        }
        __syncthreads();

        // ---- compute: 4 k-steps of k16 ----
#pragma unroll
        for (int ks = 0; ks < 4; ks++) {
            const int k0 = ks * 16;
            uint32_t ah[2][4], al[2][4];
#pragma unroll
            for (int mi = 0; mi < 2; mi++) {
                uint32_t off = (uint32_t)((warp_m * 32 + mi * 16 + arow) * 72 + k0 + acol8) * 2;
                ldmx4(ah[mi], u_ash + off);
                ldmx4(al[mi], u_asl + off);
            }
            uint32_t bh[3][4], bl[3][4];
#pragma unroll
            for (int nj = 0; nj < 3; nj++) {
                uint32_t off = (uint32_t)((warp_n * 48 + nj * 16 + brow) * 72 + k0 + bcol8) * 2;
                ldmx4(bh[nj], u_bsh + off);
                ldmx4(bl[nj], u_bsl + off);
            }
#pragma unroll
            for (int mi = 0; mi < 2; mi++)
#pragma unroll
                for (int n8 = 0; n8 < 6; n8++) {
                    uint32_t b0h = bh[n8 >> 1][(n8 & 1) * 2];
                    uint32_t b1h = bh[n8 >> 1][(n8 & 1) * 2 + 1];
                    uint32_t b0l = bl[n8 >> 1][(n8 & 1) * 2];
                    uint32_t b1l = bl[n8 >> 1][(n8 & 1) * 2 + 1];
                    mma_bf16(acc[mi][n8], ah[mi], b0h, b1h);
                    mma_bf16(acc[mi][n8], ah[mi], b0l, b1l);
                    mma_bf16(acc[mi][n8], al[mi], b0h, b1h);
                }
        }
        __syncthreads();
    }

    // ---- epilogue: write g_P[pix][d] ----
    const size_t rowbase = (size_t)b * PIX_PB + c_LOFF[level] + tin * 64 + warp_m * 32;
    const int dbase = warp_n * 48 + (lane & 3) * 2;
    const int rsub = lane >> 2;
#pragma unroll
    for (int mi = 0; mi < 2; mi++) {
        size_t r0 = (rowbase + mi * 16 + rsub) * DM;
        size_t r1 = (rowbase + mi * 16 + rsub + 8) * DM;
#pragma unroll
        for (int n8 = 0; n8 < 6; n8++) {
            int d = dbase + n8 * 8;
            *(float2*)(g_P + r0 + d) = make_float2(acc[mi][n8][0], acc[mi][n8][1]);
            *(float2*)(g_P + r1 + d) = make_float2(acc[mi][n8][2], acc[mi][n8][3]);
        }
    }
}

// ---------------------------------------------------------------------------
// Kernel 4: PE GEMMs (fp32 f32x2). z=0: peW = PE @ Wseed_pe^T ; z=1: pos
// ---------------------------------------------------------------------------
__global__ void __launch_bounds__(256) k_pegemm(const float* __restrict__ Wpos_b,
                                                float* __restrict__ out_pos) {
    __shared__ float Fs[32][68];
    __shared__ float Ws[32][192];

    const int z = blockIdx.y;
    const int p0 = blockIdx.x * 64;
    const int tid = threadIdx.x;
    const int tx = tid & 15, ty = tid >> 4;

#pragma unroll
    for (int i = 0; i < 8; i++) {
        int idx = tid + 256 * i;
        int m = idx >> 5, j = idx & 31;
        Fs[j][m] = g_PE[(size_t)(p0 + m) * PEW + j];
    }
    const float* Wsrc = z ? g_WposT : (g_Wt + 768 * DM);
    float* wsf = &Ws[0][0];
#pragma unroll
    for (int i = 0; i < 24; i++) {
        int idx = tid + 256 * i;
        wsf[idx] = Wsrc[idx];
    }
    __syncthreads();

    unsigned long long acc[4][6];
#pragma unroll
    for (int m = 0; m < 4; m++)
#pragma unroll
        for (int q = 0; q < 6; q++) acc[m][q] = 0ULL;

#pragma unroll 8
    for (int kc = 0; kc < 32; kc++) {
        float4 xv = *(const float4*)&Fs[kc][ty * 4];
        mk_step(xv, &Ws[kc][tx * 12], acc);
    }

#pragma unroll
    for (int m = 0; m < 4; m++) {
        float o[12];
#pragma unroll
        for (int q = 0; q < 6; q++) unpack2(acc[m][q], o[2 * q], o[2 * q + 1]);
        size_t row = (size_t)(p0 + ty * 4 + m) * DM + tx * 12;
        if (z == 0) {
            float* dst = g_peW + row;
            *(float4*)(dst + 0) = make_float4(o[0], o[1], o[2], o[3]);
            *(float4*)(dst + 4) = make_float4(o[4], o[5], o[6], o[7]);
            *(float4*)(dst + 8) = make_float4(o[8], o[9], o[10], o[11]);
        } else {
#pragma unroll
            for (int q = 0; q < 12; q++) o[q] += Wpos_b[tx * 12 + q];
            float* dst = out_pos + row;
            *(float4*)(dst + 0) = make_float4(o[0], o[1], o[2], o[3]);
            *(float4*)(dst + 4) = make_float4(o[4], o[5], o[6], o[7]);
            *(float4*)(dst + 8) = make_float4(o[8], o[9], o[10], o[11]);
        }
    }
}

// ---------------------------------------------------------------------------
// Kernel 5: gather + bilinear + LayerNorm (1 warp = 1 point)
// ---------------------------------------------------------------------------
__global__ void __launch_bounds__(256) k_gather(const float* __restrict__ coords,
                                                const float* __restrict__ seed_b,
                                                const float* __restrict__ lng,
                                                const float* __restrict__ lnb,
                                                float* __restrict__ out_seed) {
    const int b = blockIdx.y;
    const int wid = threadIdx.x >> 5;
    const int lane = threadIdx.x & 31;
    const int k = blockIdx.x * 8 + wid;
    const int gp = b * KPTS + k;

    const float cx = coords[(size_t)gp * 2 + 0];
    const float cy = coords[(size_t)gp * 2 + 1];
    const float gx = 2.0f * cx / 511.0f - 1.0f;
    const float gy = 2.0f * cy / 511.0f - 1.0f;

    float acc[6];
#pragma unroll
    for (int r = 0; r < 6; r++) {
        int d = r * 32 + lane;
        acc[r] = seed_b[d] + g_peW[(size_t)gp * DM + d];
    }

#pragma unroll
    for (int l = 0; l < 4; l++) {
        const int W = c_Wd[l];
        const float ix = (gx + 1.0f) * 0.5f * (float)(W - 1);
        const float iy = (gy + 1.0f) * 0.5f * (float)(W - 1);
        const float fx0 = floorf(ix);
        const float fy0 = floorf(iy);
        const float wx = ix - fx0;
        const float wy = iy - fy0;
        int x0 = min(max((int)fx0, 0), W - 1);
        int x1 = min(max((int)fx0 + 1, 0), W - 1);
        int y0 = min(max((int)fy0, 0), W - 1);
        int y1 = min(max((int)fy0 + 1, 0), W - 1);
        const float w00 = (1.0f - wx) * (1.0f - wy);
        const float w01 = wx * (1.0f - wy);
        const float w10 = (1.0f - wx) * wy;
        const float w11 = wx * wy;
        const size_t base = ((size_t)b * PIX_PB + c_LOFF[l]) * DM;
        const float* p00 = g_P + base + (size_t)(y0 * W + x0) * DM;
        const float* p01 = g_P + base + (size_t)(y0 * W + x1) * DM;
        const float* p10 = g_P + base + (size_t)(y1 * W + x0) * DM;
        const float* p11 = g_P + base + (size_t)(y1 * W + x1) * DM;
#pragma unroll
        for (int r = 0; r < 6; r++) {
            int d = r * 32 + lane;
            acc[r] += w00 * __ldg(p00 + d) + w01 * __ldg(p01 + d)
                    + w10 * __ldg(p10 + d) + w11 * __ldg(p11 + d);
        }
    }

    float s = 0.0f, s2 = 0.0f;
#pragma unroll
    for (int r = 0; r < 6; r++) { s += acc[r]; s2 += acc[r] * acc[r]; }
#pragma unroll
    for (int o = 16; o > 0; o >>= 1) {
        s  += __shfl_xor_sync(0xFFFFFFFFu, s, o);
        s2 += __shfl_xor_sync(0xFFFFFFFFu, s2, o);
    }
    const float mu = s * (1.0f / 192.0f);
    const float var = s2 * (1.0f / 192.0f) - mu * mu;
    const float inv = rsqrtf(var + 1e-5f);

    float* dst = out_seed + (size_t)gp * DM;
#pragma unroll
    for (int r = 0; r < 6; r++) {
        int d = r * 32 + lane;
        dst[d] = (acc[r] - mu) * inv * lng[d] + lnb[d];
    }
}

// ---------------------------------------------------------------------------
// launch
// ---------------------------------------------------------------------------
extern "C" void kernel_launch(void* const* d_in, const int* in_sizes, int n_in,
                              void* d_out, int out_size) {
    const float* coords  = (const float*)d_in[0];
    const float* L1      = (const float*)d_in[1];
    const float* L2      = (const float*)d_in[2];
    const float* L3      = (const float*)d_in[3];
    const float* L4      = (const float*)d_in[4];
    const float* Wseed_w = (const float*)d_in[5];
    const float* Wseed_b = (const float*)d_in[6];
    const float* ln_g    = (const float*)d_in[7];
    const float* ln_b    = (const float*)d_in[8];
    const float* Wpos_w  = (const float*)d_in[9];
    const float* Wpos_b  = (const float*)d_in[10];

    float* out      = (float*)d_out;
    float* out_seed = out;
    float* out_pos  = out + (size_t)NPTS * DM;
    float* out_cg   = out + (size_t)2 * NPTS * DM;

    cudaFuncSetAttribute(k_gemm, cudaFuncAttributeMaxDynamicSharedMemorySize, SMEM_G);

    const int prep_n = DIN * DM + PEW * DM + 4 * DM * DM;
    k_prep<<<(prep_n + 255) / 256, 256>>>(Wseed_w, Wpos_w);
    k_pe<<<(NPTS * PEW) / 256, 256>>>(coords, out_cg);
    k_gemm<<<BATCH * TPB64, 256, SMEM_G>>>(L1, L2, L3, L4);
    k_pegemm<<<dim3(NPTS / 64, 2), 256>>>(Wpos_b, out_pos);
    k_gather<<<dim3(KPTS / 8, BATCH), 256>>>(coords, Wseed_b, ln_g, ln_b, out_seed);
}

// round 4
// speedup vs baseline: 1.8087x; 1.1052x over previous
#include <cuda_runtime.h>
#include <cuda_bf16.h>
#include <cstdint>

// ---------------------------------------------------------------------------
// Problem constants
// ---------------------------------------------------------------------------
#define BATCH     8
#define KPTS      4096
#define NPTS      (BATCH * KPTS)      // 32768
#define DM        192
#define DIN       800
#define PEW       32
#define PIX_PB    21760               // 16384+4096+1024+256
#define TPB64     340                 // 64-px tiles per batch

__device__ __constant__ int c_HW[4]    = {16384, 4096, 1024, 256};
__device__ __constant__ int c_Wd[4]    = {128, 64, 32, 16};
__device__ __constant__ int c_LOFF[4]  = {0, 16384, 20480, 21504};

// ---------------------------------------------------------------------------
// Static device scratch
// ---------------------------------------------------------------------------
__device__ float g_P[(size_t)BATCH * PIX_PB * DM];    // projected maps [pix][d]
__device__ float g_PE[(size_t)NPTS * PEW];
__device__ float g_peW[(size_t)NPTS * DM];
__device__ __nv_bfloat16 g_Wbf[2][4][DM][DM];         // [hi/lo][level][d][c]
__device__ __nv_bfloat16 g_Wbfpe[2][2][DM][PEW];      // [z][hi/lo][d][j]

// ---------------------------------------------------------------------------
// PTX helpers (generic sm_80+ — safe on compute_103 target)
// ---------------------------------------------------------------------------
__device__ __forceinline__ uint32_t smem_u32(const void* p) {
    uint32_t a;
    asm("{ .reg .u64 t; cvta.to.shared.u64 t, %1; cvt.u32.u64 %0, t; }" : "=r"(a) : "l"(p));
    return a;
}
__device__ __forceinline__ void ldmx4(uint32_t r[4], uint32_t addr) {
    asm volatile("ldmatrix.sync.aligned.m8n8.x4.shared.b16 {%0,%1,%2,%3}, [%4];"
                 : "=r"(r[0]), "=r"(r[1]), "=r"(r[2]), "=r"(r[3]) : "r"(addr));
}
__device__ __forceinline__ void mma_bf16(float c[4], const uint32_t a[4],
                                         uint32_t b0, uint32_t b1) {
    asm volatile("mma.sync.aligned.m16n8k16.row.col.f32.bf16.bf16.f32 "
                 "{%0,%1,%2,%3}, {%4,%5,%6,%7}, {%8,%9}, {%0,%1,%2,%3};"
                 : "+f"(c[0]), "+f"(c[1]), "+f"(c[2]), "+f"(c[3])
                 : "r"(a[0]), "r"(a[1]), "r"(a[2]), "r"(a[3]), "r"(b0), "r"(b1));
}
#define CP_ASYNC16(dst, src) \
    asm volatile("cp.async.cg.shared.global [%0], [%1], 16;" \
                 :: "r"(dst), "l"(src) : "memory")
#define CP_COMMIT()  asm volatile("cp.async.commit_group;" ::: "memory")
#define CP_WAIT0()   asm volatile("cp.async.wait_group 0;" ::: "memory")

// ---------------------------------------------------------------------------
// Kernel 1: weight prep — bf16 hi/lo splits
// ---------------------------------------------------------------------------
#define PREP_N (4 * DM * DM + 2 * DM * PEW)
__global__ void __launch_bounds__(256) k_prep(const float* __restrict__ Wseed_w,
                                              const float* __restrict__ Wpos_w) {
    int idx = blockIdx.x * 256 + threadIdx.x;
    if (idx < 4 * DM * DM) {
        int l = idx / (DM * DM);
        int d = (idx % (DM * DM)) / DM;
        int c = idx % DM;
        float w = Wseed_w[(size_t)d * DIN + l * DM + c];
        __nv_bfloat16 h = __float2bfloat16(w);
        __nv_bfloat16 lo = __float2bfloat16(w - __bfloat162float(h));
        g_Wbf[0][l][d][c] = h;
        g_Wbf[1][l][d][c] = lo;
    } else if (idx < PREP_N) {
        int i2 = idx - 4 * DM * DM;
        int z = i2 / (DM * PEW);
        int d = (i2 % (DM * PEW)) / PEW;
        int j = i2 % PEW;
        float w = z ? Wpos_w[(size_t)d * PEW + j] : Wseed_w[(size_t)d * DIN + 768 + j];
        __nv_bfloat16 h = __float2bfloat16(w);
        __nv_bfloat16 lo = __float2bfloat16(w - __bfloat162float(h));
        g_Wbfpe[z][0][d][j] = h;
        g_Wbfpe[z][1][d][j] = lo;
    }
}

// ---------------------------------------------------------------------------
// Kernel 2: Fourier PE + center_grid
// ---------------------------------------------------------------------------
__global__ void __launch_bounds__(256) k_pe(const float* __restrict__ coords,
                                            float* __restrict__ out_cg) {
    int gid = blockIdx.x * 256 + threadIdx.x;
    int p = gid >> 5;
    int j = gid & 31;
    if (p >= NPTS) return;
    float cx = coords[(size_t)p * 2 + 0];
    float cy = coords[(size_t)p * 2 + 1];
    int grp = j >> 3;
    float f = (float)(1 << (j & 7));
    float cn = ((grp < 2) ? cx : cy) * (1.0f / 512.0f);
    float arg = (cn * f) * 6.283185307179586f;
    float val = (grp & 1) ? cosf(arg) : sinf(arg);
    g_PE[(size_t)p * PEW + j] = val;
    if (j == 0) {
        out_cg[(size_t)p * 2 + 0] = 2.0f * cx / 511.0f - 1.0f;
        out_cg[(size_t)p * 2 + 1] = 2.0f * cy / 511.0f - 1.0f;
    }
}

// ---------------------------------------------------------------------------
// Kernel 3: HMMA bf16 3-split projection GEMM, cp.async pipelined
//   P[pix][d] = sum_c F[c][pix] * Wl[d][c]   (per level)
// CTA: 64 px x 192 d, 8 warps (2m x 4n), K=192 in 3 chunks of 64.
// SMEM (dynamic, 108544B): Bs_h/Bs_l [192][72] bf16, As_h/As_l [64][72] bf16,
//                          Fs double-buffered [64][68] f32.
// ---------------------------------------------------------------------------
#define SM_BSH 0
#define SM_BSL 27648
#define SM_ASH 55296
#define SM_ASL 64512
#define SM_FS0 73728
#define FS_SZ  17408                  // 64*68*4
#define SMEM_G (SM_FS0 + 2 * FS_SZ)  // 108544

__global__ void __launch_bounds__(256, 2) k_gemm(const float* __restrict__ F0,
                                                 const float* __restrict__ F1,
                                                 const float* __restrict__ F2,
                                                 const float* __restrict__ F3) {
    extern __shared__ char smem[];
    __nv_bfloat16* As_h = (__nv_bfloat16*)(smem + SM_ASH);
    __nv_bfloat16* As_l = (__nv_bfloat16*)(smem + SM_ASL);
    const uint32_t u_base = smem_u32(smem);
    const uint32_t u_bsh = u_base + SM_BSH, u_bsl = u_base + SM_BSL;
    const uint32_t u_ash = u_base + SM_ASH, u_asl = u_base + SM_ASL;
    const uint32_t u_fs0 = u_base + SM_FS0;

    const int tid = threadIdx.x;
    const int lane = tid & 31, wid = tid >> 5;
    const int warp_m = wid & 1, warp_n = wid >> 1;

    const int b = blockIdx.x / TPB64;
    const int r = blockIdx.x % TPB64;
    int level, tin;
    if (r < 256)      { level = 0; tin = r; }
    else if (r < 320) { level = 1; tin = r - 256; }
    else if (r < 336) { level = 2; tin = r - 320; }
    else              { level = 3; tin = r - 336; }
    const int HW = c_HW[level];
    const float* F = (level == 0) ? F0 : (level == 1) ? F1 : (level == 2) ? F2 : F3;
    F += (size_t)b * DM * HW + tin * 64;
    const __nv_bfloat16* Wh = &g_Wbf[0][level][0][0];
    const __nv_bfloat16* Wl = &g_Wbf[1][level][0][0];

    float acc[2][6][4];
#pragma unroll
    for (int mi = 0; mi < 2; mi++)
#pragma unroll
        for (int n8 = 0; n8 < 6; n8++)
#pragma unroll
            for (int e = 0; e < 4; e++) acc[mi][n8][e] = 0.0f;

    const int arow = lane & 15;
    const int acol8 = (lane >> 4) << 3;
    const int brow = (lane & 7) + ((lane >> 4) << 3);
    const int bcol8 = ((lane >> 3) & 1) << 3;
    const int px_cv = tid >> 2;
    const int q_cv = tid & 3;

    // F-stage issue: chunk c0, buffer buf
    const int fc = tid >> 4, fp4 = (tid & 15) << 2;      // row, col4 (per-thread fixed)
    // per thread: 4 rows (fc, fc+16, fc+32, fc+48)
#define ISSUE_F(c0, buf) do { \
        uint32_t fdst = u_fs0 + (buf) * FS_SZ + fp4 * 4; \
        const float* fsrc = F + (size_t)((c0) + fc) * HW + fp4; \
        _Pragma("unroll") \
        for (int rr = 0; rr < 4; rr++) \
            CP_ASYNC16(fdst + (fc + rr * 16) * 272, fsrc + (size_t)(rr * 16) * HW); \
    } while (0)
    // B issue: chunk c0 (hi+lo), 6 x uint4 per thread per array
    const int bd = tid >> 1, bu0 = (tid & 1) << 2;       // d-base, u-base
#define ISSUE_B(c0) do { \
        _Pragma("unroll") \
        for (int ii = 0; ii < 6; ii++) { \
            int d = bd + (ii >> 1) * 64, u = bu0 + (ii & 1) * 4 * 0 + (ii & 1) * 0; \
            (void)u; \
            int uu = bu0; \
            uint32_t off = (uint32_t)(d * 144 + (uu + (ii & 1) * 0) * 0); (void)off; \
        } \
    } while (0)
    // (simpler explicit B issue below)
#undef ISSUE_B
#define ISSUE_B(c0) do { \
        _Pragma("unroll") \
        for (int ii = tid; ii < 1536; ii += 256) { \
            int d = ii >> 3, u = ii & 7; \
            uint32_t off = (uint32_t)(d * 144 + u * 16); \
            CP_ASYNC16(u_bsh + off, Wh + d * DM + (c0) + u * 8); \
            CP_ASYNC16(u_bsl + off, Wl + d * DM + (c0) + u * 8); \
        } \
    } while (0)

    // prologue
    ISSUE_F(0, 0);
    ISSUE_B(0);
    CP_COMMIT();

    for (int cz = 0; cz < 3; cz++) {
        const int c0 = cz * 64;
        const int buf = cz & 1;
        CP_WAIT0();
        __syncthreads();
        if (cz < 2) { ISSUE_F(c0 + 64, buf ^ 1); CP_COMMIT(); }

        // convert Fs[buf] -> As hi/lo (transpose c<->px)
        const float* Fsb = (const float*)(smem + SM_FS0 + buf * FS_SZ);
#pragma unroll
        for (int g = 0; g < 2; g++) {
            union { unsigned short s[8]; uint4 v; } uh, ul;
#pragma unroll
            for (int e = 0; e < 8; e++) {
                int c = q_cv * 16 + g * 8 + e;
                float v = Fsb[c * 68 + px_cv];
                __nv_bfloat16 h = __float2bfloat16(v);
                __nv_bfloat16 lo = __float2bfloat16(v - __bfloat162float(h));
                uh.s[e] = *(unsigned short*)&h;
                ul.s[e] = *(unsigned short*)&lo;
            }
            *(uint4*)(As_h + px_cv * 72 + q_cv * 16 + g * 8) = uh.v;
            *(uint4*)(As_l + px_cv * 72 + q_cv * 16 + g * 8) = ul.v;
        }
        __syncthreads();

        // compute 4 k-steps
#pragma unroll
        for (int ks = 0; ks < 4; ks++) {
            const int k0 = ks * 16;
            uint32_t ah[2][4], al[2][4];
#pragma unroll
            for (int mi = 0; mi < 2; mi++) {
                uint32_t off = (uint32_t)((warp_m * 32 + mi * 16 + arow) * 72 + k0 + acol8) * 2;
                ldmx4(ah[mi], u_ash + off);
                ldmx4(al[mi], u_asl + off);
            }
            uint32_t bh[3][4], bl[3][4];
#pragma unroll
            for (int nj = 0; nj < 3; nj++) {
                uint32_t off = (uint32_t)((warp_n * 48 + nj * 16 + brow) * 72 + k0 + bcol8) * 2;
                ldmx4(bh[nj], u_bsh + off);
                ldmx4(bl[nj], u_bsl + off);
            }
#pragma unroll
            for (int mi = 0; mi < 2; mi++)
#pragma unroll
                for (int n8 = 0; n8 < 6; n8++) {
                    uint32_t b0h = bh[n8 >> 1][(n8 & 1) * 2];
                    uint32_t b1h = bh[n8 >> 1][(n8 & 1) * 2 + 1];
                    uint32_t b0l = bl[n8 >> 1][(n8 & 1) * 2];
                    uint32_t b1l = bl[n8 >> 1][(n8 & 1) * 2 + 1];
                    mma_bf16(acc[mi][n8], ah[mi], b0h, b1h);
                    mma_bf16(acc[mi][n8], ah[mi], b0l, b1l);
                    mma_bf16(acc[mi][n8], al[mi], b0h, b1h);
                }
        }
        __syncthreads();
        if (cz < 2) { ISSUE_B(c0 + 64); CP_COMMIT(); }
    }

    // epilogue
    const size_t rowbase = (size_t)b * PIX_PB + c_LOFF[level] + tin * 64 + warp_m * 32;
    const int dbase = warp_n * 48 + (lane & 3) * 2;
    const int rsub = lane >> 2;
#pragma unroll
    for (int mi = 0; mi < 2; mi++) {
        size_t r0 = (rowbase + mi * 16 + rsub) * DM;
        size_t r1 = (rowbase + mi * 16 + rsub + 8) * DM;
#pragma unroll
        for (int n8 = 0; n8 < 6; n8++) {
            int d = dbase + n8 * 8;
            *(float2*)(g_P + r0 + d) = make_float2(acc[mi][n8][0], acc[mi][n8][1]);
            *(float2*)(g_P + r1 + d) = make_float2(acc[mi][n8][2], acc[mi][n8][3]);
        }
    }
}

// ---------------------------------------------------------------------------
// Kernel 4: PE GEMMs via HMMA 3-split.  z=0: g_peW = PE @ Wpe^T ; z=1: pos
//   M=32768, K=32, N=192.  CTA: 64 px, 8 warps (2m x 4n), 2 k-steps.
// ---------------------------------------------------------------------------
__global__ void __launch_bounds__(256) k_pegemm(const float* __restrict__ Wpos_b,
                                                float* __restrict__ out_pos) {
    __shared__ __nv_bfloat16 Bs[2][DM * 40];    // [hi/lo][d][j] stride 40
    __shared__ __nv_bfloat16 As[2][64 * 40];    // [hi/lo][px][j]

    const int z = blockIdx.y;
    const int p0 = blockIdx.x * 64;
    const int tid = threadIdx.x;
    const int lane = tid & 31, wid = tid >> 5;
    const int warp_m = wid & 1, warp_n = wid >> 1;
    const uint32_t u_bs0 = smem_u32(&Bs[0][0]), u_bs1 = smem_u32(&Bs[1][0]);
    const uint32_t u_as0 = smem_u32(&As[0][0]), u_as1 = smem_u32(&As[1][0]);

    // load B (hi+lo): 768 uint4 per array
    const __nv_bfloat16* W0 = &g_Wbfpe[z][0][0][0];
    const __nv_bfloat16* W1 = &g_Wbfpe[z][1][0][0];
#pragma unroll
    for (int i = tid; i < 768; i += 256) {
        int d = i >> 2, u = i & 3;
        *(uint4*)(&Bs[0][d * 40 + u * 8]) = *(const uint4*)(W0 + d * PEW + u * 8);
        *(uint4*)(&Bs[1][d * 40 + u * 8]) = *(const uint4*)(W1 + d * PEW + u * 8);
    }
    // load + convert A: PE[64 px][32 j], no transpose needed
#pragma unroll
    for (int i = tid; i < 512; i += 256) {
        int p = i >> 3, j4 = (i & 7) * 4;
        float4 v = *(const float4*)(g_PE + (size_t)(p0 + p) * PEW + j4);
        union { unsigned short s[4]; uint2 u; } uh, ul;
        float vv[4] = {v.x, v.y, v.z, v.w};
#pragma unroll
        for (int e = 0; e < 4; e++) {
            __nv_bfloat16 h = __float2bfloat16(vv[e]);
            __nv_bfloat16 lo = __float2bfloat16(vv[e] - __bfloat162float(h));
            uh.s[e] = *(unsigned short*)&h;
            ul.s[e] = *(unsigned short*)&lo;
        }
        *(uint2*)(&As[0][p * 40 + j4]) = uh.u;
        *(uint2*)(&As[1][p * 40 + j4]) = ul.u;
    }
    __syncthreads();

    float acc[2][6][4];
#pragma unroll
    for (int mi = 0; mi < 2; mi++)
#pragma unroll
        for (int n8 = 0; n8 < 6; n8++)
#pragma unroll
            for (int e = 0; e < 4; e++) acc[mi][n8][e] = 0.0f;

    const int arow = lane & 15;
    const int acol8 = (lane >> 4) << 3;
    const int brow = (lane & 7) + ((lane >> 4) << 3);
    const int bcol8 = ((lane >> 3) & 1) << 3;

#pragma unroll
    for (int ks = 0; ks < 2; ks++) {
        const int k0 = ks * 16;
        uint32_t ah[2][4], al[2][4];
#pragma unroll
        for (int mi = 0; mi < 2; mi++) {
            uint32_t off = (uint32_t)((warp_m * 32 + mi * 16 + arow) * 40 + k0 + acol8) * 2;
            ldmx4(ah[mi], u_as0 + off);
            ldmx4(al[mi], u_as1 + off);
        }
        uint32_t bh[3][4], bl[3][4];
#pragma unroll
        for (int nj = 0; nj < 3; nj++) {
            uint32_t off = (uint32_t)((warp_n * 48 + nj * 16 + brow) * 40 + k0 + bcol8) * 2;
            ldmx4(bh[nj], u_bs0 + off);
            ldmx4(bl[nj], u_bs1 + off);
        }
#pragma unroll
        for (int mi = 0; mi < 2; mi++)
#pragma unroll
            for (int n8 = 0; n8 < 6; n8++) {
                uint32_t b0h = bh[n8 >> 1][(n8 & 1) * 2];
                uint32_t b1h = bh[n8 >> 1][(n8 & 1) * 2 + 1];
                uint32_t b0l = bl[n8 >> 1][(n8 & 1) * 2];
                uint32_t b1l = bl[n8 >> 1][(n8 & 1) * 2 + 1];
                mma_bf16(acc[mi][n8], ah[mi], b0h, b1h);
                mma_bf16(acc[mi][n8], ah[mi], b0l, b1l);
                mma_bf16(acc[mi][n8], al[mi], b0h, b1h);
            }
    }

    const int dbase = warp_n * 48 + (lane & 3) * 2;
    const int rsub = lane >> 2;
    const size_t rowbase = (size_t)p0 + warp_m * 32;
#pragma unroll
    for (int mi = 0; mi < 2; mi++) {
        size_t r0 = (rowbase + mi * 16 + rsub) * DM;
        size_t r1 = (rowbase + mi * 16 + rsub + 8) * DM;
#pragma unroll
        for (int n8 = 0; n8 < 6; n8++) {
            int d = dbase + n8 * 8;
            if (z == 0) {
                *(float2*)(g_peW + r0 + d) = make_float2(acc[mi][n8][0], acc[mi][n8][1]);
                *(float2*)(g_peW + r1 + d) = make_float2(acc[mi][n8][2], acc[mi][n8][3]);
            } else {
                float b0 = __ldg(Wpos_b + d), b1 = __ldg(Wpos_b + d + 1);
                *(float2*)(out_pos + r0 + d) = make_float2(acc[mi][n8][0] + b0,
                                                           acc[mi][n8][1] + b1);
                *(float2*)(out_pos + r1 + d) = make_float2(acc[mi][n8][2] + b0,
                                                           acc[mi][n8][3] + b1);
            }
        }
    }
}

// ---------------------------------------------------------------------------
// Kernel 5: gather + bilinear + LayerNorm (1 warp = 1 point, vectorized)
// lane owns d = lane*4..lane*4+3 (float4) and d = 128+lane*2, +1 (float2)
// ---------------------------------------------------------------------------
__global__ void __launch_bounds__(256) k_gather(const float* __restrict__ coords,
                                                const float* __restrict__ seed_b,
                                                const float* __restrict__ lng,
                                                const float* __restrict__ lnb,
                                                float* __restrict__ out_seed) {
    const int b = blockIdx.y;
    const int wid = threadIdx.x >> 5;
    const int lane = threadIdx.x & 31;
    const int k = blockIdx.x * 8 + wid;
    const int gp = b * KPTS + k;
    const int l4 = lane * 4;
    const int l2 = 128 + lane * 2;

    const float cx = coords[(size_t)gp * 2 + 0];
    const float cy = coords[(size_t)gp * 2 + 1];
    const float gx = 2.0f * cx / 511.0f - 1.0f;
    const float gy = 2.0f * cy / 511.0f - 1.0f;

    const float* peW = g_peW + (size_t)gp * DM;
    float4 a4;
    float2 a2;
    {
        float4 s4 = __ldg((const float4*)(seed_b + l4));
        float4 p4 = __ldg((const float4*)(peW + l4));
        a4 = make_float4(s4.x + p4.x, s4.y + p4.y, s4.z + p4.z, s4.w + p4.w);
        float2 s2 = __ldg((const float2*)(seed_b + l2));
        float2 p2 = __ldg((const float2*)(peW + l2));
        a2 = make_float2(s2.x + p2.x, s2.y + p2.y);
    }

#pragma unroll
    for (int l = 0; l < 4; l++) {
        const int W = c_Wd[l];
        const float ix = (gx + 1.0f) * 0.5f * (float)(W - 1);
        const float iy = (gy + 1.0f) * 0.5f * (float)(W - 1);
        const float fx0 = floorf(ix);
        const float fy0 = floorf(iy);
        const float wx = ix - fx0;
        const float wy = iy - fy0;
        int x0 = min(max((int)fx0, 0), W - 1);
        int x1 = min(max((int)fx0 + 1, 0), W - 1);
        int y0 = min(max((int)fy0, 0), W - 1);
        int y1 = min(max((int)fy0 + 1, 0), W - 1);
        const size_t base = ((size_t)b * PIX_PB + c_LOFF[l]) * DM;
        const float* cp[4] = {g_P + base + (size_t)(y0 * W + x0) * DM,
                              g_P + base + (size_t)(y0 * W + x1) * DM,
                              g_P + base + (size_t)(y1 * W + x0) * DM,
                              g_P + base + (size_t)(y1 * W + x1) * DM};
        const float ww[4] = {(1.0f - wx) * (1.0f - wy), wx * (1.0f - wy),
                             (1.0f - wx) * wy, wx * wy};
#pragma unroll
        for (int c = 0; c < 4; c++) {
            float4 v4 = __ldg((const float4*)(cp[c] + l4));
            float2 v2 = __ldg((const float2*)(cp[c] + l2));
            a4.x += ww[c] * v4.x; a4.y += ww[c] * v4.y;
            a4.z += ww[c] * v4.z; a4.w += ww[c] * v4.w;
            a2.x += ww[c] * v2.x; a2.y += ww[c] * v2.y;
        }
    }

    float s = a4.x + a4.y + a4.z + a4.w + a2.x + a2.y;
    float s2 = a4.x * a4.x + a4.y * a4.y + a4.z * a4.z + a4.w * a4.w
             + a2.x * a2.x + a2.y * a2.y;
#pragma unroll
    for (int o = 16; o > 0; o >>= 1) {
        s  += __shfl_xor_sync(0xFFFFFFFFu, s, o);
        s2 += __shfl_xor_sync(0xFFFFFFFFu, s2, o);
    }
    const float mu = s * (1.0f / 192.0f);
    const float var = s2 * (1.0f / 192.0f) - mu * mu;
    const float inv = rsqrtf(var + 1e-5f);

    float* dst = out_seed + (size_t)gp * DM;
    {
        float4 g4 = __ldg((const float4*)(lng + l4));
        float4 b4 = __ldg((const float4*)(lnb + l4));
        float4 o4 = make_float4((a4.x - mu) * inv * g4.x + b4.x,
                                (a4.y - mu) * inv * g4.y + b4.y,
                                (a4.z - mu) * inv * g4.z + b4.z,
                                (a4.w - mu) * inv * g4.w + b4.w);
        *(float4*)(dst + l4) = o4;
        float2 g2 = __ldg((const float2*)(lng + l2));
        float2 b2 = __ldg((const float2*)(lnb + l2));
        *(float2*)(dst + l2) = make_float2((a2.x - mu) * inv * g2.x + b2.x,
                                           (a2.y - mu) * inv * g2.y + b2.y);
    }
}

// ---------------------------------------------------------------------------
// launch
// ---------------------------------------------------------------------------
extern "C" void kernel_launch(void* const* d_in, const int* in_sizes, int n_in,
                              void* d_out, int out_size) {
    const float* coords  = (const float*)d_in[0];
    const float* L1      = (const float*)d_in[1];
    const float* L2      = (const float*)d_in[2];
    const float* L3      = (const float*)d_in[3];
    const float* L4      = (const float*)d_in[4];
    const float* Wseed_w = (const float*)d_in[5];
    const float* Wseed_b = (const float*)d_in[6];
    const float* ln_g    = (const float*)d_in[7];
    const float* ln_b    = (const float*)d_in[8];
    const float* Wpos_w  = (const float*)d_in[9];
    const float* Wpos_b  = (const float*)d_in[10];

    float* out      = (float*)d_out;
    float* out_seed = out;
    float* out_pos  = out + (size_t)NPTS * DM;
    float* out_cg   = out + (size_t)2 * NPTS * DM;

    cudaFuncSetAttribute(k_gemm, cudaFuncAttributeMaxDynamicSharedMemorySize, SMEM_G);

    k_prep<<<(PREP_N + 255) / 256, 256>>>(Wseed_w, Wpos_w);
    k_pe<<<(NPTS * PEW) / 256, 256>>>(coords, out_cg);
    k_gemm<<<BATCH * TPB64, 256, SMEM_G>>>(L1, L2, L3, L4);
    k_pegemm<<<dim3(NPTS / 64, 2), 256>>>(Wpos_b, out_pos);
    k_gather<<<dim3(KPTS / 8, BATCH), 256>>>(coords, Wseed_b, ln_g, ln_b, out_seed);
}

// round 5
// speedup vs baseline: 1.9995x; 1.1055x over previous
#include <cuda_runtime.h>
#include <cuda_bf16.h>
#include <cuda_fp16.h>
#include <cstdint>

// ---------------------------------------------------------------------------
// Problem constants
// ---------------------------------------------------------------------------
#define BATCH     8
#define KPTS      4096
#define NPTS      (BATCH * KPTS)      // 32768
#define DM        192
#define DIN       800
#define PEW       32
#define PIX_PB    21760               // 16384+4096+1024+256
#define TPB64     340                 // 64-px tiles per batch

__device__ __constant__ int c_HW[4]    = {16384, 4096, 1024, 256};
__device__ __constant__ int c_Wd[4]    = {128, 64, 32, 16};
__device__ __constant__ int c_LOFF[4]  = {0, 16384, 20480, 21504};

// ---------------------------------------------------------------------------
// Static device scratch
// ---------------------------------------------------------------------------
__device__ __half g_P[(size_t)BATCH * PIX_PB * DM];   // projected maps [pix][d] fp16 (67MB)
__device__ float g_peW[(size_t)NPTS * DM];            // PE @ Wseed_pe^T (25MB)
__device__ __nv_bfloat16 g_Wbf[2][4][DM][DM];         // [hi/lo][level][d][c]
__device__ __nv_bfloat16 g_Wbfpe[2][2][DM][PEW];      // [z][hi/lo][d][j]

// ---------------------------------------------------------------------------
// PTX helpers (generic sm_80+ — safe on compute_103 target)
// ---------------------------------------------------------------------------
__device__ __forceinline__ uint32_t smem_u32(const void* p) {
    uint32_t a;
    asm("{ .reg .u64 t; cvta.to.shared.u64 t, %1; cvt.u32.u64 %0, t; }" : "=r"(a) : "l"(p));
    return a;
}
__device__ __forceinline__ void ldmx4(uint32_t r[4], uint32_t addr) {
    asm volatile("ldmatrix.sync.aligned.m8n8.x4.shared.b16 {%0,%1,%2,%3}, [%4];"
                 : "=r"(r[0]), "=r"(r[1]), "=r"(r[2]), "=r"(r[3]) : "r"(addr));
}
__device__ __forceinline__ void mma_bf16(float c[4], const uint32_t a[4],
                                         uint32_t b0, uint32_t b1) {
    asm volatile("mma.sync.aligned.m16n8k16.row.col.f32.bf16.bf16.f32 "
                 "{%0,%1,%2,%3}, {%4,%5,%6,%7}, {%8,%9}, {%0,%1,%2,%3};"
                 : "+f"(c[0]), "+f"(c[1]), "+f"(c[2]), "+f"(c[3])
                 : "r"(a[0]), "r"(a[1]), "r"(a[2]), "r"(a[3]), "r"(b0), "r"(b1));
}
#define CP_ASYNC16(dst, src) \
    asm volatile("cp.async.cg.shared.global [%0], [%1], 16;" \
                 :: "r"(dst), "l"(src) : "memory")
#define CP_COMMIT()  asm volatile("cp.async.commit_group;" ::: "memory")
#define CP_WAIT0()   asm volatile("cp.async.wait_group 0;" ::: "memory")

// ---------------------------------------------------------------------------
// Kernel 1: weight prep — bf16 hi/lo splits
// ---------------------------------------------------------------------------
#define PREP_N (4 * DM * DM + 2 * DM * PEW)
__global__ void __launch_bounds__(256) k_prep(const float* __restrict__ Wseed_w,
                                              const float* __restrict__ Wpos_w) {
    int idx = blockIdx.x * 256 + threadIdx.x;
    if (idx < 4 * DM * DM) {
        int l = idx / (DM * DM);
        int d = (idx % (DM * DM)) / DM;
        int c = idx % DM;
        float w = Wseed_w[(size_t)d * DIN + l * DM + c];
        __nv_bfloat16 h = __float2bfloat16(w);
        __nv_bfloat16 lo = __float2bfloat16(w - __bfloat162float(h));
        g_Wbf[0][l][d][c] = h;
        g_Wbf[1][l][d][c] = lo;
    } else if (idx < PREP_N) {
        int i2 = idx - 4 * DM * DM;
        int z = i2 / (DM * PEW);
        int d = (i2 % (DM * PEW)) / PEW;
        int j = i2 % PEW;
        float w = z ? Wpos_w[(size_t)d * PEW + j] : Wseed_w[(size_t)d * DIN + 768 + j];
        __nv_bfloat16 h = __float2bfloat16(w);
        __nv_bfloat16 lo = __float2bfloat16(w - __bfloat162float(h));
        g_Wbfpe[z][0][d][j] = h;
        g_Wbfpe[z][1][d][j] = lo;
    }
}

// ---------------------------------------------------------------------------
// Kernel 2: HMMA bf16 3-split projection GEMM, cp.async pipelined, fp16 out
//   P[pix][d] = sum_c F[c][pix] * Wl[d][c]   (per level)
// CTA: 64 px x 192 d, 8 warps (2m x 4n), K=192 in 3 chunks of 64.
// ---------------------------------------------------------------------------
#define SM_BSH 0
#define SM_BSL 27648
#define SM_ASH 55296
#define SM_ASL 64512
#define SM_FS0 73728
#define FS_SZ  17408                  // 64*68*4
#define SMEM_G (SM_FS0 + 2 * FS_SZ)  // 108544

__global__ void __launch_bounds__(256, 2) k_gemm(const float* __restrict__ F0,
                                                 const float* __restrict__ F1,
                                                 const float* __restrict__ F2,
                                                 const float* __restrict__ F3) {
    extern __shared__ char smem[];
    __nv_bfloat16* As_h = (__nv_bfloat16*)(smem + SM_ASH);
    __nv_bfloat16* As_l = (__nv_bfloat16*)(smem + SM_ASL);
    const uint32_t u_base = smem_u32(smem);
    const uint32_t u_bsh = u_base + SM_BSH, u_bsl = u_base + SM_BSL;
    const uint32_t u_ash = u_base + SM_ASH, u_asl = u_base + SM_ASL;
    const uint32_t u_fs0 = u_base + SM_FS0;

    const int tid = threadIdx.x;
    const int lane = tid & 31, wid = tid >> 5;
    const int warp_m = wid & 1, warp_n = wid >> 1;

    const int b = blockIdx.x / TPB64;
    const int r = blockIdx.x % TPB64;
    int level, tin;
    if (r < 256)      { level = 0; tin = r; }
    else if (r < 320) { level = 1; tin = r - 256; }
    else if (r < 336) { level = 2; tin = r - 320; }
    else              { level = 3; tin = r - 336; }
    const int HW = c_HW[level];
    const float* F = (level == 0) ? F0 : (level == 1) ? F1 : (level == 2) ? F2 : F3;
    F += (size_t)b * DM * HW + tin * 64;
    const __nv_bfloat16* Wh = &g_Wbf[0][level][0][0];
    const __nv_bfloat16* Wl = &g_Wbf[1][level][0][0];

    float acc[2][6][4];
#pragma unroll
    for (int mi = 0; mi < 2; mi++)
#pragma unroll
        for (int n8 = 0; n8 < 6; n8++)
#pragma unroll
            for (int e = 0; e < 4; e++) acc[mi][n8][e] = 0.0f;

    const int arow = lane & 15;
    const int acol8 = (lane >> 4) << 3;
    const int brow = (lane & 7) + ((lane >> 4) << 3);
    const int bcol8 = ((lane >> 3) & 1) << 3;
    const int px_cv = tid >> 2;
    const int q_cv = tid & 3;

    const int fc = tid >> 4, fp4 = (tid & 15) << 2;
#define ISSUE_F(c0, buf) do { \
        uint32_t fdst = u_fs0 + (buf) * FS_SZ + fp4 * 4; \
        const float* fsrc = F + (size_t)((c0) + fc) * HW + fp4; \
        _Pragma("unroll") \
        for (int rr = 0; rr < 4; rr++) \
            CP_ASYNC16(fdst + (fc + rr * 16) * 272, fsrc + (size_t)(rr * 16) * HW); \
    } while (0)
#define ISSUE_B(c0) do { \
        _Pragma("unroll") \
        for (int ii = tid; ii < 1536; ii += 256) { \
            int d = ii >> 3, u = ii & 7; \
            uint32_t off = (uint32_t)(d * 144 + u * 16); \
            CP_ASYNC16(u_bsh + off, Wh + d * DM + (c0) + u * 8); \
            CP_ASYNC16(u_bsl + off, Wl + d * DM + (c0) + u * 8); \
        } \
    } while (0)

    ISSUE_F(0, 0);
    ISSUE_B(0);
    CP_COMMIT();

    for (int cz = 0; cz < 3; cz++) {
        const int c0 = cz * 64;
        const int buf = cz & 1;
        CP_WAIT0();
        __syncthreads();
        if (cz < 2) { ISSUE_F(c0 + 64, buf ^ 1); CP_COMMIT(); }

        const float* Fsb = (const float*)(smem + SM_FS0 + buf * FS_SZ);
#pragma unroll
        for (int g = 0; g < 2; g++) {
            union { unsigned short s[8]; uint4 v; } uh, ul;
#pragma unroll
            for (int e = 0; e < 8; e++) {
                int c = q_cv * 16 + g * 8 + e;
                float v = Fsb[c * 68 + px_cv];
                __nv_bfloat16 h = __float2bfloat16(v);
                __nv_bfloat16 lo = __float2bfloat16(v - __bfloat162float(h));
                uh.s[e] = *(unsigned short*)&h;
                ul.s[e] = *(unsigned short*)&lo;
            }
            *(uint4*)(As_h + px_cv * 72 + q_cv * 16 + g * 8) = uh.v;
            *(uint4*)(As_l + px_cv * 72 + q_cv * 16 + g * 8) = ul.v;
        }
        __syncthreads();

#pragma unroll
        for (int ks = 0; ks < 4; ks++) {
            const int k0 = ks * 16;
            uint32_t ah[2][4], al[2][4];
#pragma unroll
            for (int mi = 0; mi < 2; mi++) {
                uint32_t off = (uint32_t)((warp_m * 32 + mi * 16 + arow) * 72 + k0 + acol8) * 2;
                ldmx4(ah[mi], u_ash + off);
                ldmx4(al[mi], u_asl + off);
            }
            uint32_t bh[3][4], bl[3][4];
#pragma unroll
            for (int nj = 0; nj < 3; nj++) {
                uint32_t off = (uint32_t)((warp_n * 48 + nj * 16 + brow) * 72 + k0 + bcol8) * 2;
                ldmx4(bh[nj], u_bsh + off);
                ldmx4(bl[nj], u_bsl + off);
            }
#pragma unroll
            for (int mi = 0; mi < 2; mi++)
#pragma unroll
                for (int n8 = 0; n8 < 6; n8++) {
                    uint32_t b0h = bh[n8 >> 1][(n8 & 1) * 2];
                    uint32_t b1h = bh[n8 >> 1][(n8 & 1) * 2 + 1];
                    uint32_t b0l = bl[n8 >> 1][(n8 & 1) * 2];
                    uint32_t b1l = bl[n8 >> 1][(n8 & 1) * 2 + 1];
                    mma_bf16(acc[mi][n8], ah[mi], b0h, b1h);
                    mma_bf16(acc[mi][n8], ah[mi], b0l, b1l);
                    mma_bf16(acc[mi][n8], al[mi], b0h, b1h);
                }
        }
        __syncthreads();
        if (cz < 2) { ISSUE_B(c0 + 64); CP_COMMIT(); }
    }

    // epilogue: fp16 writes
    const size_t rowbase = (size_t)b * PIX_PB + c_LOFF[level] + tin * 64 + warp_m * 32;
    const int dbase = warp_n * 48 + (lane & 3) * 2;
    const int rsub = lane >> 2;
#pragma unroll
    for (int mi = 0; mi < 2; mi++) {
        size_t r0 = (rowbase + mi * 16 + rsub) * DM;
        size_t r1 = (rowbase + mi * 16 + rsub + 8) * DM;
#pragma unroll
        for (int n8 = 0; n8 < 6; n8++) {
            int d = dbase + n8 * 8;
            *(__half2*)(g_P + r0 + d) = __floats2half2_rn(acc[mi][n8][0], acc[mi][n8][1]);
            *(__half2*)(g_P + r1 + d) = __floats2half2_rn(acc[mi][n8][2], acc[mi][n8][3]);
        }
    }
}

// ---------------------------------------------------------------------------
// Kernel 3: fused PE + dual GEMM + center_grid.
//   Per CTA (64 points): compute PE in SMEM (bf16 hi/lo), then
//   z=0: g_peW = PE @ Wseed_pe^T ;  z=1: out_pos = PE @ Wpos^T + b.
//   A fragments shared across both z. Also writes center_grid.
// SMEM layout (dynamic, 72192B):
//   As0 @0 (5120)  As1 @5120  Bs[z][hl] @10240+z*30720+hl*15360  coords @71680
// ---------------------------------------------------------------------------
#define PG_AS0 0
#define PG_AS1 5120
#define PG_BS(z, hl) (10240 + (z) * 30720 + (hl) * 15360)
#define PG_CS  71680
#define SMEM_PE 72192

__global__ void __launch_bounds__(256) k_pegemm(const float* __restrict__ coords,
                                                const float* __restrict__ Wpos_b,
                                                float* __restrict__ out_pos,
                                                float* __restrict__ out_cg) {
    extern __shared__ char smem[];
    __nv_bfloat16* As0 = (__nv_bfloat16*)(smem + PG_AS0);
    __nv_bfloat16* As1 = (__nv_bfloat16*)(smem + PG_AS1);
    float* cs = (float*)(smem + PG_CS);
    const uint32_t u_base = smem_u32(smem);

    const int p0 = blockIdx.x * 64;
    const int tid = threadIdx.x;
    const int lane = tid & 31, wid = tid >> 5;
    const int warp_m = wid & 1, warp_n = wid >> 1;

    // stage coords
    if (tid < 128) cs[tid] = coords[(size_t)p0 * 2 + tid];
    // load B (4 arrays)
#pragma unroll
    for (int i = tid; i < 768; i += 256) {
        int d = i >> 2, u = i & 3;
#pragma unroll
        for (int z = 0; z < 2; z++)
#pragma unroll
            for (int hl = 0; hl < 2; hl++)
                *(uint4*)(smem + PG_BS(z, hl) + (d * 40 + u * 8) * 2) =
                    *(const uint4*)(&g_Wbfpe[z][hl][d][0] + u * 8);
    }
    __syncthreads();

    // compute PE -> As (hi/lo). i indexes (point, side, freq); sincos shared.
#pragma unroll
    for (int i = tid; i < 1024; i += 256) {
        int p = i >> 4, k = i & 15;
        int s = k >> 3, fq = k & 7;
        float c = cs[p * 2 + s];
        float arg = c * (1.0f / 512.0f) * (float)(1 << fq) * 6.283185307179586f;
        float sv, cv;
        sincosf(arg, &sv, &cv);
        int js = s * 16 + fq, jc = js + 8;
        __nv_bfloat16 sh = __float2bfloat16(sv);
        __nv_bfloat16 sl = __float2bfloat16(sv - __bfloat162float(sh));
        __nv_bfloat16 ch = __float2bfloat16(cv);
        __nv_bfloat16 cl = __float2bfloat16(cv - __bfloat162float(ch));
        As0[p * 40 + js] = sh; As1[p * 40 + js] = sl;
        As0[p * 40 + jc] = ch; As1[p * 40 + jc] = cl;
    }
    // center grid
    if (tid < 64) {
        int gp = p0 + tid;
        out_cg[(size_t)gp * 2 + 0] = 2.0f * cs[tid * 2 + 0] / 511.0f - 1.0f;
        out_cg[(size_t)gp * 2 + 1] = 2.0f * cs[tid * 2 + 1] / 511.0f - 1.0f;
    }
    __syncthreads();

    const int arow = lane & 15;
    const int acol8 = (lane >> 4) << 3;
    const int brow = (lane & 7) + ((lane >> 4) << 3);
    const int bcol8 = ((lane >> 3) & 1) << 3;

    // A fragments (shared across z)
    uint32_t ah[2][2][4], al[2][2][4];   // [ks][mi]
#pragma unroll
    for (int ks = 0; ks < 2; ks++)
#pragma unroll
        for (int mi = 0; mi < 2; mi++) {
            uint32_t off = (uint32_t)((warp_m * 32 + mi * 16 + arow) * 40 + ks * 16 + acol8) * 2;
            ldmx4(ah[ks][mi], u_base + PG_AS0 + off);
            ldmx4(al[ks][mi], u_base + PG_AS1 + off);
        }

    const int dbase = warp_n * 48 + (lane & 3) * 2;
    const int rsub = lane >> 2;

#pragma unroll
    for (int z = 0; z < 2; z++) {
        float acc[2][6][4];
#pragma unroll
        for (int mi = 0; mi < 2; mi++)
#pragma unroll
            for (int n8 = 0; n8 < 6; n8++)
#pragma unroll
                for (int e = 0; e < 4; e++) acc[mi][n8][e] = 0.0f;

#pragma unroll
        for (int ks = 0; ks < 2; ks++) {
            uint32_t bh[3][4], bl[3][4];
#pragma unroll
            for (int nj = 0; nj < 3; nj++) {
                uint32_t off = (uint32_t)((warp_n * 48 + nj * 16 + brow) * 40 + ks * 16 + bcol8) * 2;
                ldmx4(bh[nj], u_base + PG_BS(z, 0) + off);
                ldmx4(bl[nj], u_base + PG_BS(z, 1) + off);
            }
#pragma unroll
            for (int mi = 0; mi < 2; mi++)
#pragma unroll
                for (int n8 = 0; n8 < 6; n8++) {
                    uint32_t b0h = bh[n8 >> 1][(n8 & 1) * 2];
                    uint32_t b1h = bh[n8 >> 1][(n8 & 1) * 2 + 1];
                    uint32_t b0l = bl[n8 >> 1][(n8 & 1) * 2];
                    uint32_t b1l = bl[n8 >> 1][(n8 & 1) * 2 + 1];
                    mma_bf16(acc[mi][n8], ah[ks][mi], b0h, b1h);
                    mma_bf16(acc[mi][n8], ah[ks][mi], b0l, b1l);
                    mma_bf16(acc[mi][n8], al[ks][mi], b0h, b1h);
                }
        }

        const size_t rowbase = (size_t)p0 + warp_m * 32;
#pragma unroll
        for (int mi = 0; mi < 2; mi++) {
            size_t r0 = (rowbase + mi * 16 + rsub) * DM;
            size_t r1 = (rowbase + mi * 16 + rsub + 8) * DM;
#pragma unroll
            for (int n8 = 0; n8 < 6; n8++) {
                int d = dbase + n8 * 8;
                if (z == 0) {
                    *(float2*)(g_peW + r0 + d) = make_float2(acc[mi][n8][0], acc[mi][n8][1]);
                    *(float2*)(g_peW + r1 + d) = make_float2(acc[mi][n8][2], acc[mi][n8][3]);
                } else {
                    float b0 = __ldg(Wpos_b + d), b1 = __ldg(Wpos_b + d + 1);
                    *(float2*)(out_pos + r0 + d) = make_float2(acc[mi][n8][0] + b0,
                                                               acc[mi][n8][1] + b1);
                    *(float2*)(out_pos + r1 + d) = make_float2(acc[mi][n8][2] + b0,
                                                               acc[mi][n8][3] + b1);
                }
            }
        }
    }
}

// ---------------------------------------------------------------------------
// Kernel 4: gather + bilinear + LayerNorm (1 warp = 1 point, fp16 g_P)
// lane owns d = lane*4..lane*4+3 and d = 128+lane*2, +1
// ---------------------------------------------------------------------------
__global__ void __launch_bounds__(256) k_gather(const float* __restrict__ coords,
                                                const float* __restrict__ seed_b,
                                                const float* __restrict__ lng,
                                                const float* __restrict__ lnb,
                                                float* __restrict__ out_seed) {
    const int b = blockIdx.y;
    const int wid = threadIdx.x >> 5;
    const int lane = threadIdx.x & 31;
    const int k = blockIdx.x * 8 + wid;
    const int gp = b * KPTS + k;
    const int l4 = lane * 4;
    const int l2 = 128 + lane * 2;

    const float cx = coords[(size_t)gp * 2 + 0];
    const float cy = coords[(size_t)gp * 2 + 1];
    const float gx = 2.0f * cx / 511.0f - 1.0f;
    const float gy = 2.0f * cy / 511.0f - 1.0f;

    const float* peW = g_peW + (size_t)gp * DM;
    float4 a4;
    float2 a2;
    {
        float4 s4 = __ldg((const float4*)(seed_b + l4));
        float4 p4 = __ldg((const float4*)(peW + l4));
        a4 = make_float4(s4.x + p4.x, s4.y + p4.y, s4.z + p4.z, s4.w + p4.w);
        float2 s2 = __ldg((const float2*)(seed_b + l2));
        float2 p2 = __ldg((const float2*)(peW + l2));
        a2 = make_float2(s2.x + p2.x, s2.y + p2.y);
    }

#pragma unroll
    for (int l = 0; l < 4; l++) {
        const int W = c_Wd[l];
        const float ix = (gx + 1.0f) * 0.5f * (float)(W - 1);
        const float iy = (gy + 1.0f) * 0.5f * (float)(W - 1);
        const float fx0 = floorf(ix);
        const float fy0 = floorf(iy);
        const float wx = ix - fx0;
        const float wy = iy - fy0;
        int x0 = min(max((int)fx0, 0), W - 1);
        int x1 = min(max((int)fx0 + 1, 0), W - 1);
        int y0 = min(max((int)fy0, 0), W - 1);
        int y1 = min(max((int)fy0 + 1, 0), W - 1);
        const size_t base = ((size_t)b * PIX_PB + c_LOFF[l]) * DM;
        const __half* cp[4] = {g_P + base + (size_t)(y0 * W + x0) * DM,
                               g_P + base + (size_t)(y0 * W + x1) * DM,
                               g_P + base + (size_t)(y1 * W + x0) * DM,
                               g_P + base + (size_t)(y1 * W + x1) * DM};
        const float ww[4] = {(1.0f - wx) * (1.0f - wy), wx * (1.0f - wy),
                             (1.0f - wx) * wy, wx * wy};
#pragma unroll
        for (int c = 0; c < 4; c++) {
            uint2 raw = __ldg((const uint2*)(cp[c] + l4));
            float2 f01 = __half22float2(*(const __half2*)&raw.x);
            float2 f23 = __half22float2(*(const __half2*)&raw.y);
            uint32_t raw2 = __ldg((const uint32_t*)(cp[c] + l2));
            float2 f45 = __half22float2(*(const __half2*)&raw2);
            a4.x += ww[c] * f01.x; a4.y += ww[c] * f01.y;
            a4.z += ww[c] * f23.x; a4.w += ww[c] * f23.y;
            a2.x += ww[c] * f45.x; a2.y += ww[c] * f45.y;
        }
    }

    float s = a4.x + a4.y + a4.z + a4.w + a2.x + a2.y;
    float s2 = a4.x * a4.x + a4.y * a4.y + a4.z * a4.z + a4.w * a4.w
             + a2.x * a2.x + a2.y * a2.y;
#pragma unroll
    for (int o = 16; o > 0; o >>= 1) {
        s  += __shfl_xor_sync(0xFFFFFFFFu, s, o);
        s2 += __shfl_xor_sync(0xFFFFFFFFu, s2, o);
    }
    const float mu = s * (1.0f / 192.0f);
    const float var = s2 * (1.0f / 192.0f) - mu * mu;
    const float inv = rsqrtf(var + 1e-5f);

    float* dst = out_seed + (size_t)gp * DM;
    {
        float4 g4 = __ldg((const float4*)(lng + l4));
        float4 b4 = __ldg((const float4*)(lnb + l4));
        float4 o4 = make_float4((a4.x - mu) * inv * g4.x + b4.x,
                                (a4.y - mu) * inv * g4.y + b4.y,
                                (a4.z - mu) * inv * g4.z + b4.z,
                                (a4.w - mu) * inv * g4.w + b4.w);
        *(float4*)(dst + l4) = o4;
        float2 g2 = __ldg((const float2*)(lng + l2));
        float2 b2 = __ldg((const float2*)(lnb + l2));
        *(float2*)(dst + l2) = make_float2((a2.x - mu) * inv * g2.x + b2.x,
                                           (a2.y - mu) * inv * g2.y + b2.y);
    }
}

// ---------------------------------------------------------------------------
// launch
// ---------------------------------------------------------------------------
extern "C" void kernel_launch(void* const* d_in, const int* in_sizes, int n_in,
                              void* d_out, int out_size) {
    const float* coords  = (const float*)d_in[0];
    const float* L1      = (const float*)d_in[1];
    const float* L2      = (const float*)d_in[2];
    const float* L3      = (const float*)d_in[3];
    const float* L4      = (const float*)d_in[4];
    const float* Wseed_w = (const float*)d_in[5];
    const float* Wseed_b = (const float*)d_in[6];
    const float* ln_g    = (const float*)d_in[7];
    const float* ln_b    = (const float*)d_in[8];
    const float* Wpos_w  = (const float*)d_in[9];
    const float* Wpos_b  = (const float*)d_in[10];

    float* out      = (float*)d_out;
    float* out_seed = out;
    float* out_pos  = out + (size_t)NPTS * DM;
    float* out_cg   = out + (size_t)2 * NPTS * DM;

    cudaFuncSetAttribute(k_gemm, cudaFuncAttributeMaxDynamicSharedMemorySize, SMEM_G);
    cudaFuncSetAttribute(k_pegemm, cudaFuncAttributeMaxDynamicSharedMemorySize, SMEM_PE);

    k_prep<<<(PREP_N + 255) / 256, 256>>>(Wseed_w, Wpos_w);
    k_gemm<<<BATCH * TPB64, 256, SMEM_G>>>(L1, L2, L3, L4);
    k_pegemm<<<NPTS / 64, 256, SMEM_PE>>>(coords, Wpos_b, out_pos, out_cg);
    k_gather<<<dim3(KPTS / 8, BATCH), 256>>>(coords, Wseed_b, ln_g, ln_b, out_seed);
}

// round 6
// speedup vs baseline: 2.2812x; 1.1409x over previous
#include <cuda_runtime.h>
#include <cuda_fp16.h>
#include <cstdint>

// ---------------------------------------------------------------------------
// Problem constants
// ---------------------------------------------------------------------------
#define BATCH     8
#define KPTS      4096
#define NPTS      (BATCH * KPTS)      // 32768
#define DM        192
#define DIN       800
#define PEW       32
#define PIX_PB    21760               // 16384+4096+1024+256
#define TPB64     340                 // 64-px tiles per batch

__device__ __constant__ int c_HW[4]    = {16384, 4096, 1024, 256};
__device__ __constant__ int c_Wd[4]    = {128, 64, 32, 16};
__device__ __constant__ int c_LOFF[4]  = {0, 16384, 20480, 21504};

// ---------------------------------------------------------------------------
// Static device scratch
// ---------------------------------------------------------------------------
__device__ __half g_P[(size_t)BATCH * PIX_PB * DM];   // projected maps [pix][d] fp16
__device__ float g_peW[(size_t)NPTS * DM];            // PE @ Wseed_pe^T
__device__ __half g_Wbf[2][4][DM][DM];                // [hi/lo][level][d][c] fp16 2-split
__device__ __half g_Wbfpe[2][2][DM][PEW];             // [z][hi/lo][d][j]

// ---------------------------------------------------------------------------
// PTX helpers (generic sm_80+ — safe on compute_103 target)
// ---------------------------------------------------------------------------
__device__ __forceinline__ uint32_t smem_u32(const void* p) {
    uint32_t a;
    asm("{ .reg .u64 t; cvta.to.shared.u64 t, %1; cvt.u32.u64 %0, t; }" : "=r"(a) : "l"(p));
    return a;
}
__device__ __forceinline__ void ldmx4(uint32_t r[4], uint32_t addr) {
    asm volatile("ldmatrix.sync.aligned.m8n8.x4.shared.b16 {%0,%1,%2,%3}, [%4];"
                 : "=r"(r[0]), "=r"(r[1]), "=r"(r[2]), "=r"(r[3]) : "r"(addr));
}
__device__ __forceinline__ void mma_f16(float c[4], const uint32_t a[4],
                                        uint32_t b0, uint32_t b1) {
    asm volatile("mma.sync.aligned.m16n8k16.row.col.f32.f16.f16.f32 "
                 "{%0,%1,%2,%3}, {%4,%5,%6,%7}, {%8,%9}, {%0,%1,%2,%3};"
                 : "+f"(c[0]), "+f"(c[1]), "+f"(c[2]), "+f"(c[3])
                 : "r"(a[0]), "r"(a[1]), "r"(a[2]), "r"(a[3]), "r"(b0), "r"(b1));
}
#define CP_ASYNC16(dst, src) \
    asm volatile("cp.async.cg.shared.global [%0], [%1], 16;" \
                 :: "r"(dst), "l"(src) : "memory")
#define CP_COMMIT()  asm volatile("cp.async.commit_group;" ::: "memory")
#define CP_WAIT0()   asm volatile("cp.async.wait_group 0;" ::: "memory")

// ---------------------------------------------------------------------------
// Kernel 1: weight prep — fp16 hi/lo 2-splits of weights
// ---------------------------------------------------------------------------
#define PREP_N (4 * DM * DM + 2 * DM * PEW)
__global__ void __launch_bounds__(256) k_prep(const float* __restrict__ Wseed_w,
                                              const float* __restrict__ Wpos_w) {
    int idx = blockIdx.x * 256 + threadIdx.x;
    if (idx < 4 * DM * DM) {
        int l = idx / (DM * DM);
        int d = (idx % (DM * DM)) / DM;
        int c = idx % DM;
        float w = Wseed_w[(size_t)d * DIN + l * DM + c];
        __half h = __float2half_rn(w);
        __half lo = __float2half_rn(w - __half2float(h));
        g_Wbf[0][l][d][c] = h;
        g_Wbf[1][l][d][c] = lo;
    } else if (idx < PREP_N) {
        int i2 = idx - 4 * DM * DM;
        int z = i2 / (DM * PEW);
        int d = (i2 % (DM * PEW)) / PEW;
        int j = i2 % PEW;
        float w = z ? Wpos_w[(size_t)d * PEW + j] : Wseed_w[(size_t)d * DIN + 768 + j];
        __half h = __float2half_rn(w);
        __half lo = __float2half_rn(w - __half2float(h));
        g_Wbfpe[z][0][d][j] = h;
        g_Wbfpe[z][1][d][j] = lo;
    }
}

// ---------------------------------------------------------------------------
// Kernel 2: HMMA fp16 projection GEMM (A single fp16, B 2-split), fp16 out
//   P[pix][d] = sum_c F[c][pix] * Wl[d][c]   (per level)
// CTA: 64 px x 192 d, 8 warps (2m x 4n), K=192 in 3 chunks of 64.
// ---------------------------------------------------------------------------
#define SM_BSH 0
#define SM_BSL 27648
#define SM_ASH 55296                  // [64][72] half = 9216
#define SM_FS0 64512
#define FS_SZ  17408                  // 64*68*4
#define SMEM_G (SM_FS0 + 2 * FS_SZ)  // 99328

__global__ void __launch_bounds__(256, 2) k_gemm(const float* __restrict__ F0,
                                                 const float* __restrict__ F1,
                                                 const float* __restrict__ F2,
                                                 const float* __restrict__ F3) {
    extern __shared__ char smem[];
    __half* As_h = (__half*)(smem + SM_ASH);
    const uint32_t u_base = smem_u32(smem);
    const uint32_t u_bsh = u_base + SM_BSH, u_bsl = u_base + SM_BSL;
    const uint32_t u_ash = u_base + SM_ASH;
    const uint32_t u_fs0 = u_base + SM_FS0;

    const int tid = threadIdx.x;
    const int lane = tid & 31, wid = tid >> 5;
    const int warp_m = wid & 1, warp_n = wid >> 1;

    const int b = blockIdx.x / TPB64;
    const int r = blockIdx.x % TPB64;
    int level, tin;
    if (r < 256)      { level = 0; tin = r; }
    else if (r < 320) { level = 1; tin = r - 256; }
    else if (r < 336) { level = 2; tin = r - 320; }
    else              { level = 3; tin = r - 336; }
    const int HW = c_HW[level];
    const float* F = (level == 0) ? F0 : (level == 1) ? F1 : (level == 2) ? F2 : F3;
    F += (size_t)b * DM * HW + tin * 64;
    const __half* Wh = &g_Wbf[0][level][0][0];
    const __half* Wl = &g_Wbf[1][level][0][0];

    float acc[2][6][4];
#pragma unroll
    for (int mi = 0; mi < 2; mi++)
#pragma unroll
        for (int n8 = 0; n8 < 6; n8++)
#pragma unroll
            for (int e = 0; e < 4; e++) acc[mi][n8][e] = 0.0f;

    const int arow = lane & 15;
    const int acol8 = (lane >> 4) << 3;
    const int brow = (lane & 7) + ((lane >> 4) << 3);
    const int bcol8 = ((lane >> 3) & 1) << 3;
    const int px_cv = tid >> 2;
    const int q_cv = tid & 3;

    const int fc = tid >> 4, fp4 = (tid & 15) << 2;
#define ISSUE_F(c0, buf) do { \
        uint32_t fdst = u_fs0 + (buf) * FS_SZ + fp4 * 4; \
        const float* fsrc = F + (size_t)((c0) + fc) * HW + fp4; \
        _Pragma("unroll") \
        for (int rr = 0; rr < 4; rr++) \
            CP_ASYNC16(fdst + (fc + rr * 16) * 272, fsrc + (size_t)(rr * 16) * HW); \
    } while (0)
#define ISSUE_B(c0) do { \
        _Pragma("unroll") \
        for (int ii = tid; ii < 1536; ii += 256) { \
            int d = ii >> 3, u = ii & 7; \
            uint32_t off = (uint32_t)(d * 144 + u * 16); \
            CP_ASYNC16(u_bsh + off, Wh + d * DM + (c0) + u * 8); \
            CP_ASYNC16(u_bsl + off, Wl + d * DM + (c0) + u * 8); \
        } \
    } while (0)

    ISSUE_F(0, 0);
    ISSUE_B(0);
    CP_COMMIT();

    for (int cz = 0; cz < 3; cz++) {
        const int c0 = cz * 64;
        const int buf = cz & 1;
        CP_WAIT0();
        __syncthreads();
        if (cz < 2) { ISSUE_F(c0 + 64, buf ^ 1); CP_COMMIT(); }

        // convert Fs[buf] -> As fp16 (transpose c<->px)
        const float* Fsb = (const float*)(smem + SM_FS0 + buf * FS_SZ);
#pragma unroll
        for (int g = 0; g < 2; g++) {
            union { unsigned short s[8]; uint4 v; } uh;
#pragma unroll
            for (int e = 0; e < 8; e++) {
                int c = q_cv * 16 + g * 8 + e;
                __half h = __float2half_rn(Fsb[c * 68 + px_cv]);
                uh.s[e] = *(unsigned short*)&h;
            }
            *(uint4*)(As_h + px_cv * 72 + q_cv * 16 + g * 8) = uh.v;
        }
        __syncthreads();

#pragma unroll
        for (int ks = 0; ks < 4; ks++) {
            const int k0 = ks * 16;
            uint32_t ah[2][4];
#pragma unroll
            for (int mi = 0; mi < 2; mi++) {
                uint32_t off = (uint32_t)((warp_m * 32 + mi * 16 + arow) * 72 + k0 + acol8) * 2;
                ldmx4(ah[mi], u_ash + off);
            }
            uint32_t bh[3][4], bl[3][4];
#pragma unroll
            for (int nj = 0; nj < 3; nj++) {
                uint32_t off = (uint32_t)((warp_n * 48 + nj * 16 + brow) * 72 + k0 + bcol8) * 2;
                ldmx4(bh[nj], u_bsh + off);
                ldmx4(bl[nj], u_bsl + off);
            }
#pragma unroll
            for (int mi = 0; mi < 2; mi++)
#pragma unroll
                for (int n8 = 0; n8 < 6; n8++) {
                    uint32_t b0h = bh[n8 >> 1][(n8 & 1) * 2];
                    uint32_t b1h = bh[n8 >> 1][(n8 & 1) * 2 + 1];
                    uint32_t b0l = bl[n8 >> 1][(n8 & 1) * 2];
                    uint32_t b1l = bl[n8 >> 1][(n8 & 1) * 2 + 1];
                    mma_f16(acc[mi][n8], ah[mi], b0h, b1h);
                    mma_f16(acc[mi][n8], ah[mi], b0l, b1l);
                }
        }
        __syncthreads();
        if (cz < 2) { ISSUE_B(c0 + 64); CP_COMMIT(); }
    }

    // epilogue: fp16 writes
    const size_t rowbase = (size_t)b * PIX_PB + c_LOFF[level] + tin * 64 + warp_m * 32;
    const int dbase = warp_n * 48 + (lane & 3) * 2;
    const int rsub = lane >> 2;
#pragma unroll
    for (int mi = 0; mi < 2; mi++) {
        size_t r0 = (rowbase + mi * 16 + rsub) * DM;
        size_t r1 = (rowbase + mi * 16 + rsub + 8) * DM;
#pragma unroll
        for (int n8 = 0; n8 < 6; n8++) {
            int d = dbase + n8 * 8;
            *(__half2*)(g_P + r0 + d) = __floats2half2_rn(acc[mi][n8][0], acc[mi][n8][1]);
            *(__half2*)(g_P + r1 + d) = __floats2half2_rn(acc[mi][n8][2], acc[mi][n8][3]);
        }
    }
}

// ---------------------------------------------------------------------------
// Kernel 3: fused PE + dual GEMM + center_grid (A single fp16, B 2-split)
// SMEM: As0 @0 (5120)  Bs[z][hl] @5120+... (15360 each)  coords @66560
// ---------------------------------------------------------------------------
#define PG_AS0 0
#define PG_BS(z, hl) (5120 + ((z) * 2 + (hl)) * 15360)
#define PG_CS  66560
#define SMEM_PE 67072

__global__ void __launch_bounds__(256) k_pegemm(const float* __restrict__ coords,
                                                const float* __restrict__ Wpos_b,
                                                float* __restrict__ out_pos,
                                                float* __restrict__ out_cg) {
    extern __shared__ char smem[];
    __half* As0 = (__half*)(smem + PG_AS0);
    float* cs = (float*)(smem + PG_CS);
    const uint32_t u_base = smem_u32(smem);

    const int p0 = blockIdx.x * 64;
    const int tid = threadIdx.x;
    const int lane = tid & 31, wid = tid >> 5;
    const int warp_m = wid & 1, warp_n = wid >> 1;

    if (tid < 128) cs[tid] = coords[(size_t)p0 * 2 + tid];
#pragma unroll
    for (int i = tid; i < 768; i += 256) {
        int d = i >> 2, u = i & 3;
#pragma unroll
        for (int z = 0; z < 2; z++)
#pragma unroll
            for (int hl = 0; hl < 2; hl++)
                *(uint4*)(smem + PG_BS(z, hl) + (d * 40 + u * 8) * 2) =
                    *(const uint4*)(&g_Wbfpe[z][hl][d][0] + u * 8);
    }
    __syncthreads();

    // compute PE -> As fp16
#pragma unroll
    for (int i = tid; i < 1024; i += 256) {
        int p = i >> 4, k = i & 15;
        int s = k >> 3, fq = k & 7;
        float c = cs[p * 2 + s];
        float arg = c * (1.0f / 512.0f) * (float)(1 << fq) * 6.283185307179586f;
        float sv, cv;
        sincosf(arg, &sv, &cv);
        int js = s * 16 + fq, jc = js + 8;
        As0[p * 40 + js] = __float2half_rn(sv);
        As0[p * 40 + jc] = __float2half_rn(cv);
    }
    if (tid < 64) {
        int gp = p0 + tid;
        out_cg[(size_t)gp * 2 + 0] = 2.0f * cs[tid * 2 + 0] / 511.0f - 1.0f;
        out_cg[(size_t)gp * 2 + 1] = 2.0f * cs[tid * 2 + 1] / 511.0f - 1.0f;
    }
    __syncthreads();

    const int arow = lane & 15;
    const int acol8 = (lane >> 4) << 3;
    const int brow = (lane & 7) + ((lane >> 4) << 3);
    const int bcol8 = ((lane >> 3) & 1) << 3;

    uint32_t ah[2][2][4];   // [ks][mi]
#pragma unroll
    for (int ks = 0; ks < 2; ks++)
#pragma unroll
        for (int mi = 0; mi < 2; mi++) {
            uint32_t off = (uint32_t)((warp_m * 32 + mi * 16 + arow) * 40 + ks * 16 + acol8) * 2;
            ldmx4(ah[ks][mi], u_base + PG_AS0 + off);
        }

    const int dbase = warp_n * 48 + (lane & 3) * 2;
    const int rsub = lane >> 2;

#pragma unroll
    for (int z = 0; z < 2; z++) {
        float acc[2][6][4];
#pragma unroll
        for (int mi = 0; mi < 2; mi++)
#pragma unroll
            for (int n8 = 0; n8 < 6; n8++)
#pragma unroll
                for (int e = 0; e < 4; e++) acc[mi][n8][e] = 0.0f;

#pragma unroll
        for (int ks = 0; ks < 2; ks++) {
            uint32_t bh[3][4], bl[3][4];
#pragma unroll
            for (int nj = 0; nj < 3; nj++) {
                uint32_t off = (uint32_t)((warp_n * 48 + nj * 16 + brow) * 40 + ks * 16 + bcol8) * 2;
                ldmx4(bh[nj], u_base + PG_BS(z, 0) + off);
                ldmx4(bl[nj], u_base + PG_BS(z, 1) + off);
            }
#pragma unroll
            for (int mi = 0; mi < 2; mi++)
#pragma unroll
                for (int n8 = 0; n8 < 6; n8++) {
                    uint32_t b0h = bh[n8 >> 1][(n8 & 1) * 2];
                    uint32_t b1h = bh[n8 >> 1][(n8 & 1) * 2 + 1];
                    uint32_t b0l = bl[n8 >> 1][(n8 & 1) * 2];
                    uint32_t b1l = bl[n8 >> 1][(n8 & 1) * 2 + 1];
                    mma_f16(acc[mi][n8], ah[ks][mi], b0h, b1h);
                    mma_f16(acc[mi][n8], ah[ks][mi], b0l, b1l);
                }
        }

        const size_t rowbase = (size_t)p0 + warp_m * 32;
#pragma unroll
        for (int mi = 0; mi < 2; mi++) {
            size_t r0 = (rowbase + mi * 16 + rsub) * DM;
            size_t r1 = (rowbase + mi * 16 + rsub + 8) * DM;
#pragma unroll
            for (int n8 = 0; n8 < 6; n8++) {
                int d = dbase + n8 * 8;
                if (z == 0) {
                    *(float2*)(g_peW + r0 + d) = make_float2(acc[mi][n8][0], acc[mi][n8][1]);
                    *(float2*)(g_peW + r1 + d) = make_float2(acc[mi][n8][2], acc[mi][n8][3]);
                } else {
                    float b0 = __ldg(Wpos_b + d), b1 = __ldg(Wpos_b + d + 1);
                    *(float2*)(out_pos + r0 + d) = make_float2(acc[mi][n8][0] + b0,
                                                               acc[mi][n8][1] + b1);
                    *(float2*)(out_pos + r1 + d) = make_float2(acc[mi][n8][2] + b0,
                                                               acc[mi][n8][3] + b1);
                }
            }
        }
    }
}

// ---------------------------------------------------------------------------
// Kernel 4: gather + bilinear + LayerNorm (1 warp = 1 point, fp16 g_P)
// ---------------------------------------------------------------------------
__global__ void __launch_bounds__(256) k_gather(const float* __restrict__ coords,
                                                const float* __restrict__ seed_b,
                                                const float* __restrict__ lng,
                                                const float* __restrict__ lnb,
                                                float* __restrict__ out_seed) {
    const int b = blockIdx.y;
    const int wid = threadIdx.x >> 5;
    const int lane = threadIdx.x & 31;
    const int k = blockIdx.x * 8 + wid;
    const int gp = b * KPTS + k;
    const int l4 = lane * 4;
    const int l2 = 128 + lane * 2;

    const float cx = coords[(size_t)gp * 2 + 0];
    const float cy = coords[(size_t)gp * 2 + 1];
    const float gx = 2.0f * cx / 511.0f - 1.0f;
    const float gy = 2.0f * cy / 511.0f - 1.0f;

    const float* peW = g_peW + (size_t)gp * DM;
    float4 a4;
    float2 a2;
    {
        float4 s4 = __ldg((const float4*)(seed_b + l4));
        float4 p4 = __ldg((const float4*)(peW + l4));
        a4 = make_float4(s4.x + p4.x, s4.y + p4.y, s4.z + p4.z, s4.w + p4.w);
        float2 s2 = __ldg((const float2*)(seed_b + l2));
        float2 p2 = __ldg((const float2*)(peW + l2));
        a2 = make_float2(s2.x + p2.x, s2.y + p2.y);
    }

#pragma unroll
    for (int l = 0; l < 4; l++) {
        const int W = c_Wd[l];
        const float ix = (gx + 1.0f) * 0.5f * (float)(W - 1);
        const float iy = (gy + 1.0f) * 0.5f * (float)(W - 1);
        const float fx0 = floorf(ix);
        const float fy0 = floorf(iy);
        const float wx = ix - fx0;
        const float wy = iy - fy0;
        int x0 = min(max((int)fx0, 0), W - 1);
        int x1 = min(max((int)fx0 + 1, 0), W - 1);
        int y0 = min(max((int)fy0, 0), W - 1);
        int y1 = min(max((int)fy0 + 1, 0), W - 1);
        const size_t base = ((size_t)b * PIX_PB + c_LOFF[l]) * DM;
        const __half* cp[4] = {g_P + base + (size_t)(y0 * W + x0) * DM,
                               g_P + base + (size_t)(y0 * W + x1) * DM,
                               g_P + base + (size_t)(y1 * W + x0) * DM,
                               g_P + base + (size_t)(y1 * W + x1) * DM};
        const float ww[4] = {(1.0f - wx) * (1.0f - wy), wx * (1.0f - wy),
                             (1.0f - wx) * wy, wx * wy};
#pragma unroll
        for (int c = 0; c < 4; c++) {
            uint2 raw = __ldg((const uint2*)(cp[c] + l4));
            float2 f01 = __half22float2(*(const __half2*)&raw.x);
            float2 f23 = __half22float2(*(const __half2*)&raw.y);
            uint32_t raw2 = __ldg((const uint32_t*)(cp[c] + l2));
            float2 f45 = __half22float2(*(const __half2*)&raw2);
            a4.x += ww[c] * f01.x; a4.y += ww[c] * f01.y;
            a4.z += ww[c] * f23.x; a4.w += ww[c] * f23.y;
            a2.x += ww[c] * f45.x; a2.y += ww[c] * f45.y;
        }
    }

    float s = a4.x + a4.y + a4.z + a4.w + a2.x + a2.y;
    float s2 = a4.x * a4.x + a4.y * a4.y + a4.z * a4.z + a4.w * a4.w
             + a2.x * a2.x + a2.y * a2.y;
#pragma unroll
    for (int o = 16; o > 0; o >>= 1) {
        s  += __shfl_xor_sync(0xFFFFFFFFu, s, o);
        s2 += __shfl_xor_sync(0xFFFFFFFFu, s2, o);
    }
    const float mu = s * (1.0f / 192.0f);
    const float var = s2 * (1.0f / 192.0f) - mu * mu;
    const float inv = rsqrtf(var + 1e-5f);

    float* dst = out_seed + (size_t)gp * DM;
    {
        float4 g4 = __ldg((const float4*)(lng + l4));
        float4 b4 = __ldg((const float4*)(lnb + l4));
        float4 o4 = make_float4((a4.x - mu) * inv * g4.x + b4.x,
                                (a4.y - mu) * inv * g4.y + b4.y,
                                (a4.z - mu) * inv * g4.z + b4.z,
                                (a4.w - mu) * inv * g4.w + b4.w);
        *(float4*)(dst + l4) = o4;
        float2 g2 = __ldg((const float2*)(lng + l2));
        float2 b2 = __ldg((const float2*)(lnb + l2));
        *(float2*)(dst + l2) = make_float2((a2.x - mu) * inv * g2.x + b2.x,
                                           (a2.y - mu) * inv * g2.y + b2.y);
    }
}

// ---------------------------------------------------------------------------
// launch
// ---------------------------------------------------------------------------
extern "C" void kernel_launch(void* const* d_in, const int* in_sizes, int n_in,
                              void* d_out, int out_size) {
    const float* coords  = (const float*)d_in[0];
    const float* L1      = (const float*)d_in[1];
    const float* L2      = (const float*)d_in[2];
    const float* L3      = (const float*)d_in[3];
    const float* L4      = (const float*)d_in[4];
    const float* Wseed_w = (const float*)d_in[5];
    const float* Wseed_b = (const float*)d_in[6];
    const float* ln_g    = (const float*)d_in[7];
    const float* ln_b    = (const float*)d_in[8];
    const float* Wpos_w  = (const float*)d_in[9];
    const float* Wpos_b  = (const float*)d_in[10];

    float* out      = (float*)d_out;
    float* out_seed = out;
    float* out_pos  = out + (size_t)NPTS * DM;
    float* out_cg   = out + (size_t)2 * NPTS * DM;

    cudaFuncSetAttribute(k_gemm, cudaFuncAttributeMaxDynamicSharedMemorySize, SMEM_G);
    cudaFuncSetAttribute(k_pegemm, cudaFuncAttributeMaxDynamicSharedMemorySize, SMEM_PE);

    k_prep<<<(PREP_N + 255) / 256, 256>>>(Wseed_w, Wpos_w);
    k_gemm<<<BATCH * TPB64, 256, SMEM_G>>>(L1, L2, L3, L4);
    k_pegemm<<<NPTS / 64, 256, SMEM_PE>>>(coords, Wpos_b, out_pos, out_cg);
    k_gather<<<dim3(KPTS / 8, BATCH), 256>>>(coords, Wseed_b, ln_g, ln_b, out_seed);
}

// round 7
// speedup vs baseline: 2.8299x; 1.2405x over previous
#include <cuda_runtime.h>
#include <cuda_fp16.h>
#include <cstdint>

// ---------------------------------------------------------------------------
// Problem constants
// ---------------------------------------------------------------------------
#define BATCH     8
#define KPTS      4096
#define NPTS      (BATCH * KPTS)      // 32768
#define DM        192
#define DIN       800
#define PEW       32
#define PIX_PB    21760               // 16384+4096+1024+256
#define TPB64     340                 // 64-px tiles per batch

__device__ __constant__ int c_HW[4]    = {16384, 4096, 1024, 256};
__device__ __constant__ int c_Wd[4]    = {128, 64, 32, 16};
__device__ __constant__ int c_LOFF[4]  = {0, 16384, 20480, 21504};

// ---------------------------------------------------------------------------
// Static device scratch
// ---------------------------------------------------------------------------
__device__ __half g_P[(size_t)BATCH * PIX_PB * DM];   // projected maps [pix][d] fp16
__device__ float g_peW[(size_t)NPTS * DM];            // PE @ Wseed_pe^T
__device__ __half g_Wbf[4][DM][DM];                   // [level][d][c] fp16
__device__ __half g_Wbfpe[2][DM][PEW];                // [z][d][j]

// ---------------------------------------------------------------------------
// PTX helpers (generic sm_80+ — safe on compute_103 target)
// ---------------------------------------------------------------------------
__device__ __forceinline__ uint32_t smem_u32(const void* p) {
    uint32_t a;
    asm("{ .reg .u64 t; cvta.to.shared.u64 t, %1; cvt.u32.u64 %0, t; }" : "=r"(a) : "l"(p));
    return a;
}
__device__ __forceinline__ void ldmx4(uint32_t r[4], uint32_t addr) {
    asm volatile("ldmatrix.sync.aligned.m8n8.x4.shared.b16 {%0,%1,%2,%3}, [%4];"
                 : "=r"(r[0]), "=r"(r[1]), "=r"(r[2]), "=r"(r[3]) : "r"(addr));
}
__device__ __forceinline__ void mma_f16(float c[4], const uint32_t a[4],
                                        uint32_t b0, uint32_t b1) {
    asm volatile("mma.sync.aligned.m16n8k16.row.col.f32.f16.f16.f32 "
                 "{%0,%1,%2,%3}, {%4,%5,%6,%7}, {%8,%9}, {%0,%1,%2,%3};"
                 : "+f"(c[0]), "+f"(c[1]), "+f"(c[2]), "+f"(c[3])
                 : "r"(a[0]), "r"(a[1]), "r"(a[2]), "r"(a[3]), "r"(b0), "r"(b1));
}
#define CP_ASYNC16(dst, src) \
    asm volatile("cp.async.cg.shared.global [%0], [%1], 16;" \
                 :: "r"(dst), "l"(src) : "memory")
#define CP_COMMIT()  asm volatile("cp.async.commit_group;" ::: "memory")
#define CP_WAIT0()   asm volatile("cp.async.wait_group 0;" ::: "memory")

// ---------------------------------------------------------------------------
// Kernel 1: weight prep — fp16 weights
// ---------------------------------------------------------------------------
#define PREP_N (4 * DM * DM + 2 * DM * PEW)
__global__ void __launch_bounds__(256) k_prep(const float* __restrict__ Wseed_w,
                                              const float* __restrict__ Wpos_w) {
    int idx = blockIdx.x * 256 + threadIdx.x;
    if (idx < 4 * DM * DM) {
        int l = idx / (DM * DM);
        int d = (idx % (DM * DM)) / DM;
        int c = idx % DM;
        ((__half*)g_Wbf)[idx] = __float2half_rn(Wseed_w[(size_t)d * DIN + l * DM + c]);
    } else if (idx < PREP_N) {
        int i2 = idx - 4 * DM * DM;
        int z = i2 / (DM * PEW);
        int d = (i2 % (DM * PEW)) / PEW;
        int j = i2 % PEW;
        float w = z ? Wpos_w[(size_t)d * PEW + j] : Wseed_w[(size_t)d * DIN + 768 + j];
        g_Wbfpe[z][d][j] = __float2half_rn(w);
    }
}

// ---------------------------------------------------------------------------
// Kernel 2: HMMA fp16 projection GEMM, cp.async pipelined, fp16 out
//   P[pix][d] = sum_c F[c][pix] * Wl[d][c]   (per level)
// CTA: 64 px x 192 d, 8 warps (2m x 4n), K=192 in 3 chunks of 64.
// ---------------------------------------------------------------------------
#define SM_BSH 0
#define SM_ASH 27648                  // [64][72] half = 9216
#define SM_FS0 36864
#define FS_SZ  17408                  // 64*68*4
#define SMEM_G (SM_FS0 + 2 * FS_SZ)  // 71680

__global__ void __launch_bounds__(256, 2) k_gemm(const float* __restrict__ F0,
                                                 const float* __restrict__ F1,
                                                 const float* __restrict__ F2,
                                                 const float* __restrict__ F3) {
    extern __shared__ char smem[];
    __half* As_h = (__half*)(smem + SM_ASH);
    const uint32_t u_base = smem_u32(smem);
    const uint32_t u_bsh = u_base + SM_BSH;
    const uint32_t u_ash = u_base + SM_ASH;
    const uint32_t u_fs0 = u_base + SM_FS0;

    const int tid = threadIdx.x;
    const int lane = tid & 31, wid = tid >> 5;
    const int warp_m = wid & 1, warp_n = wid >> 1;

    const int b = blockIdx.x / TPB64;
    const int r = blockIdx.x % TPB64;
    int level, tin;
    if (r < 256)      { level = 0; tin = r; }
    else if (r < 320) { level = 1; tin = r - 256; }
    else if (r < 336) { level = 2; tin = r - 320; }
    else              { level = 3; tin = r - 336; }
    const int HW = c_HW[level];
    const float* F = (level == 0) ? F0 : (level == 1) ? F1 : (level == 2) ? F2 : F3;
    F += (size_t)b * DM * HW + tin * 64;
    const __half* Wh = &g_Wbf[level][0][0];

    float acc[2][6][4];
#pragma unroll
    for (int mi = 0; mi < 2; mi++)
#pragma unroll
        for (int n8 = 0; n8 < 6; n8++)
#pragma unroll
            for (int e = 0; e < 4; e++) acc[mi][n8][e] = 0.0f;

    const int arow = lane & 15;
    const int acol8 = (lane >> 4) << 3;
    const int brow = (lane & 7) + ((lane >> 4) << 3);
    const int bcol8 = ((lane >> 3) & 1) << 3;
    const int px_cv = tid >> 2;
    const int q_cv = tid & 3;

    const int fc = tid >> 4, fp4 = (tid & 15) << 2;
#define ISSUE_F(c0, buf) do { \
        uint32_t fdst = u_fs0 + (buf) * FS_SZ + fp4 * 4; \
        const float* fsrc = F + (size_t)((c0) + fc) * HW + fp4; \
        _Pragma("unroll") \
        for (int rr = 0; rr < 4; rr++) \
            CP_ASYNC16(fdst + (fc + rr * 16) * 272, fsrc + (size_t)(rr * 16) * HW); \
    } while (0)
#define ISSUE_B(c0) do { \
        _Pragma("unroll") \
        for (int ii = tid; ii < 1536; ii += 256) { \
            int d = ii >> 3, u = ii & 7; \
            uint32_t off = (uint32_t)(d * 144 + u * 16); \
            CP_ASYNC16(u_bsh + off, Wh + d * DM + (c0) + u * 8); \
        } \
    } while (0)

    ISSUE_F(0, 0);
    ISSUE_B(0);
    CP_COMMIT();

    for (int cz = 0; cz < 3; cz++) {
        const int c0 = cz * 64;
        const int buf = cz & 1;
        CP_WAIT0();
        __syncthreads();
        if (cz < 2) { ISSUE_F(c0 + 64, buf ^ 1); CP_COMMIT(); }

        // convert Fs[buf] -> As fp16 (transpose c<->px)
        const float* Fsb = (const float*)(smem + SM_FS0 + buf * FS_SZ);
#pragma unroll
        for (int g = 0; g < 2; g++) {
            union { unsigned short s[8]; uint4 v; } uh;
#pragma unroll
            for (int e = 0; e < 8; e++) {
                int c = q_cv * 16 + g * 8 + e;
                __half h = __float2half_rn(Fsb[c * 68 + px_cv]);
                uh.s[e] = *(unsigned short*)&h;
            }
            *(uint4*)(As_h + px_cv * 72 + q_cv * 16 + g * 8) = uh.v;
        }
        __syncthreads();

#pragma unroll
        for (int ks = 0; ks < 4; ks++) {
            const int k0 = ks * 16;
            uint32_t ah[2][4];
#pragma unroll
            for (int mi = 0; mi < 2; mi++) {
                uint32_t off = (uint32_t)((warp_m * 32 + mi * 16 + arow) * 72 + k0 + acol8) * 2;
                ldmx4(ah[mi], u_ash + off);
            }
            uint32_t bh[3][4];
#pragma unroll
            for (int nj = 0; nj < 3; nj++) {
                uint32_t off = (uint32_t)((warp_n * 48 + nj * 16 + brow) * 72 + k0 + bcol8) * 2;
                ldmx4(bh[nj], u_bsh + off);
            }
#pragma unroll
            for (int mi = 0; mi < 2; mi++)
#pragma unroll
                for (int n8 = 0; n8 < 6; n8++) {
                    uint32_t b0h = bh[n8 >> 1][(n8 & 1) * 2];
                    uint32_t b1h = bh[n8 >> 1][(n8 & 1) * 2 + 1];
                    mma_f16(acc[mi][n8], ah[mi], b0h, b1h);
                }
        }
        __syncthreads();
        if (cz < 2) { ISSUE_B(c0 + 64); CP_COMMIT(); }
    }

    // epilogue: fp16 writes
    const size_t rowbase = (size_t)b * PIX_PB + c_LOFF[level] + tin * 64 + warp_m * 32;
    const int dbase = warp_n * 48 + (lane & 3) * 2;
    const int rsub = lane >> 2;
#pragma unroll
    for (int mi = 0; mi < 2; mi++) {
        size_t r0 = (rowbase + mi * 16 + rsub) * DM;
        size_t r1 = (rowbase + mi * 16 + rsub + 8) * DM;
#pragma unroll
        for (int n8 = 0; n8 < 6; n8++) {
            int d = dbase + n8 * 8;
            *(__half2*)(g_P + r0 + d) = __floats2half2_rn(acc[mi][n8][0], acc[mi][n8][1]);
            *(__half2*)(g_P + r1 + d) = __floats2half2_rn(acc[mi][n8][2], acc[mi][n8][3]);
        }
    }
}

// ---------------------------------------------------------------------------
// Kernel 3: fused PE + dual GEMM + center_grid (fp16 x fp16)
// SMEM: As0 @0 (5120)  Bs[z] @5120+z*15360  coords @35840
// ---------------------------------------------------------------------------
#define PG_AS0 0
#define PG_BS(z) (5120 + (z) * 15360)
#define PG_CS  35840
#define SMEM_PE 36352

__global__ void __launch_bounds__(256) k_pegemm(const float* __restrict__ coords,
                                                const float* __restrict__ Wpos_b,
                                                float* __restrict__ out_pos,
                                                float* __restrict__ out_cg) {
    extern __shared__ char smem[];
    __half* As0 = (__half*)(smem + PG_AS0);
    float* cs = (float*)(smem + PG_CS);
    const uint32_t u_base = smem_u32(smem);

    const int p0 = blockIdx.x * 64;
    const int tid = threadIdx.x;
    const int lane = tid & 31, wid = tid >> 5;
    const int warp_m = wid & 1, warp_n = wid >> 1;

    if (tid < 128) cs[tid] = coords[(size_t)p0 * 2 + tid];
#pragma unroll
    for (int i = tid; i < 768; i += 256) {
        int d = i >> 2, u = i & 3;
#pragma unroll
        for (int z = 0; z < 2; z++)
            *(uint4*)(smem + PG_BS(z) + (d * 40 + u * 8) * 2) =
                *(const uint4*)(&g_Wbfpe[z][d][0] + u * 8);
    }
    __syncthreads();

    // compute PE -> As fp16
#pragma unroll
    for (int i = tid; i < 1024; i += 256) {
        int p = i >> 4, k = i & 15;
        int s = k >> 3, fq = k & 7;
        float c = cs[p * 2 + s];
        float arg = c * (1.0f / 512.0f) * (float)(1 << fq) * 6.283185307179586f;
        float sv, cv;
        sincosf(arg, &sv, &cv);
        int js = s * 16 + fq, jc = js + 8;
        As0[p * 40 + js] = __float2half_rn(sv);
        As0[p * 40 + jc] = __float2half_rn(cv);
    }
    if (tid < 64) {
        int gp = p0 + tid;
        out_cg[(size_t)gp * 2 + 0] = 2.0f * cs[tid * 2 + 0] / 511.0f - 1.0f;
        out_cg[(size_t)gp * 2 + 1] = 2.0f * cs[tid * 2 + 1] / 511.0f - 1.0f;
    }
    __syncthreads();

    const int arow = lane & 15;
    const int acol8 = (lane >> 4) << 3;
    const int brow = (lane & 7) + ((lane >> 4) << 3);
    const int bcol8 = ((lane >> 3) & 1) << 3;

    uint32_t ah[2][2][4];   // [ks][mi]
#pragma unroll
    for (int ks = 0; ks < 2; ks++)
#pragma unroll
        for (int mi = 0; mi < 2; mi++) {
            uint32_t off = (uint32_t)((warp_m * 32 + mi * 16 + arow) * 40 + ks * 16 + acol8) * 2;
            ldmx4(ah[ks][mi], u_base + PG_AS0 + off);
        }

    const int dbase = warp_n * 48 + (lane & 3) * 2;
    const int rsub = lane >> 2;

#pragma unroll
    for (int z = 0; z < 2; z++) {
        float acc[2][6][4];
#pragma unroll
        for (int mi = 0; mi < 2; mi++)
#pragma unroll
            for (int n8 = 0; n8 < 6; n8++)
#pragma unroll
                for (int e = 0; e < 4; e++) acc[mi][n8][e] = 0.0f;

#pragma unroll
        for (int ks = 0; ks < 2; ks++) {
            uint32_t bh[3][4];
#pragma unroll
            for (int nj = 0; nj < 3; nj++) {
                uint32_t off = (uint32_t)((warp_n * 48 + nj * 16 + brow) * 40 + ks * 16 + bcol8) * 2;
                ldmx4(bh[nj], u_base + PG_BS(z) + off);
            }
#pragma unroll
            for (int mi = 0; mi < 2; mi++)
#pragma unroll
                for (int n8 = 0; n8 < 6; n8++) {
                    uint32_t b0h = bh[n8 >> 1][(n8 & 1) * 2];
                    uint32_t b1h = bh[n8 >> 1][(n8 & 1) * 2 + 1];
                    mma_f16(acc[mi][n8], ah[ks][mi], b0h, b1h);
                }
        }

        const size_t rowbase = (size_t)p0 + warp_m * 32;
#pragma unroll
        for (int mi = 0; mi < 2; mi++) {
            size_t r0 = (rowbase + mi * 16 + rsub) * DM;
            size_t r1 = (rowbase + mi * 16 + rsub + 8) * DM;
#pragma unroll
            for (int n8 = 0; n8 < 6; n8++) {
                int d = dbase + n8 * 8;
                if (z == 0) {
                    *(float2*)(g_peW + r0 + d) = make_float2(acc[mi][n8][0], acc[mi][n8][1]);
                    *(float2*)(g_peW + r1 + d) = make_float2(acc[mi][n8][2], acc[mi][n8][3]);
                } else {
                    float b0 = __ldg(Wpos_b + d), b1 = __ldg(Wpos_b + d + 1);
                    *(float2*)(out_pos + r0 + d) = make_float2(acc[mi][n8][0] + b0,
                                                               acc[mi][n8][1] + b1);
                    *(float2*)(out_pos + r1 + d) = make_float2(acc[mi][n8][2] + b0,
                                                               acc[mi][n8][3] + b1);
                }
            }
        }
    }
}

// ---------------------------------------------------------------------------
// Kernel 4: gather + bilinear + LayerNorm (1 warp = 1 point, fp16 g_P)
// ---------------------------------------------------------------------------
__global__ void __launch_bounds__(256) k_gather(const float* __restrict__ coords,
                                                const float* __restrict__ seed_b,
                                                const float* __restrict__ lng,
                                                const float* __restrict__ lnb,
                                                float* __restrict__ out_seed) {
    const int b = blockIdx.y;
    const int wid = threadIdx.x >> 5;
    const int lane = threadIdx.x & 31;
    const int k = blockIdx.x * 8 + wid;
    const int gp = b * KPTS + k;
    const int l4 = lane * 4;
    const int l2 = 128 + lane * 2;

    const float cx = coords[(size_t)gp * 2 + 0];
    const float cy = coords[(size_t)gp * 2 + 1];
    const float gx = 2.0f * cx / 511.0f - 1.0f;
    const float gy = 2.0f * cy / 511.0f - 1.0f;

    const float* peW = g_peW + (size_t)gp * DM;
    float4 a4;
    float2 a2;
    {
        float4 s4 = __ldg((const float4*)(seed_b + l4));
        float4 p4 = __ldg((const float4*)(peW + l4));
        a4 = make_float4(s4.x + p4.x, s4.y + p4.y, s4.z + p4.z, s4.w + p4.w);
        float2 s2 = __ldg((const float2*)(seed_b + l2));
        float2 p2 = __ldg((const float2*)(peW + l2));
        a2 = make_float2(s2.x + p2.x, s2.y + p2.y);
    }

#pragma unroll
    for (int l = 0; l < 4; l++) {
        const int W = c_Wd[l];
        const float ix = (gx + 1.0f) * 0.5f * (float)(W - 1);
        const float iy = (gy + 1.0f) * 0.5f * (float)(W - 1);
        const float fx0 = floorf(ix);
        const float fy0 = floorf(iy);
        const float wx = ix - fx0;
        const float wy = iy - fy0;
        int x0 = min(max((int)fx0, 0), W - 1);
        int x1 = min(max((int)fx0 + 1, 0), W - 1);
        int y0 = min(max((int)fy0, 0), W - 1);
        int y1 = min(max((int)fy0 + 1, 0), W - 1);
        const size_t base = ((size_t)b * PIX_PB + c_LOFF[l]) * DM;
        const __half* cp[4] = {g_P + base + (size_t)(y0 * W + x0) * DM,
                               g_P + base + (size_t)(y0 * W + x1) * DM,
                               g_P + base + (size_t)(y1 * W + x0) * DM,
                               g_P + base + (size_t)(y1 * W + x1) * DM};
        const float ww[4] = {(1.0f - wx) * (1.0f - wy), wx * (1.0f - wy),
                             (1.0f - wx) * wy, wx * wy};
#pragma unroll
        for (int c = 0; c < 4; c++) {
            uint2 raw = __ldg((const uint2*)(cp[c] + l4));
            float2 f01 = __half22float2(*(const __half2*)&raw.x);
            float2 f23 = __half22float2(*(const __half2*)&raw.y);
            uint32_t raw2 = __ldg((const uint32_t*)(cp[c] + l2));
            float2 f45 = __half22float2(*(const __half2*)&raw2);
            a4.x += ww[c] * f01.x; a4.y += ww[c] * f01.y;
            a4.z += ww[c] * f23.x; a4.w += ww[c] * f23.y;
            a2.x += ww[c] * f45.x; a2.y += ww[c] * f45.y;
        }
    }

    float s = a4.x + a4.y + a4.z + a4.w + a2.x + a2.y;
    float s2 = a4.x * a4.x + a4.y * a4.y + a4.z * a4.z + a4.w * a4.w
             + a2.x * a2.x + a2.y * a2.y;
#pragma unroll
    for (int o = 16; o > 0; o >>= 1) {
        s  += __shfl_xor_sync(0xFFFFFFFFu, s, o);
        s2 += __shfl_xor_sync(0xFFFFFFFFu, s2, o);
    }
    const float mu = s * (1.0f / 192.0f);
    const float var = s2 * (1.0f / 192.0f) - mu * mu;
    const float inv = rsqrtf(var + 1e-5f);

    float* dst = out_seed + (size_t)gp * DM;
    {
        float4 g4 = __ldg((const float4*)(lng + l4));
        float4 b4 = __ldg((const float4*)(lnb + l4));
        float4 o4 = make_float4((a4.x - mu) * inv * g4.x + b4.x,
                                (a4.y - mu) * inv * g4.y + b4.y,
                                (a4.z - mu) * inv * g4.z + b4.z,
                                (a4.w - mu) * inv * g4.w + b4.w);
        *(float4*)(dst + l4) = o4;
        float2 g2 = __ldg((const float2*)(lng + l2));
        float2 b2 = __ldg((const float2*)(lnb + l2));
        *(float2*)(dst + l2) = make_float2((a2.x - mu) * inv * g2.x + b2.x,
                                           (a2.y - mu) * inv * g2.y + b2.y);
    }
}

// ---------------------------------------------------------------------------
// launch
// ---------------------------------------------------------------------------
extern "C" void kernel_launch(void* const* d_in, const int* in_sizes, int n_in,
                              void* d_out, int out_size) {
    const float* coords  = (const float*)d_in[0];
    const float* L1      = (const float*)d_in[1];
    const float* L2      = (const float*)d_in[2];
    const float* L3      = (const float*)d_in[3];
    const float* L4      = (const float*)d_in[4];
    const float* Wseed_w = (const float*)d_in[5];
    const float* Wseed_b = (const float*)d_in[6];
    const float* ln_g    = (const float*)d_in[7];
    const float* ln_b    = (const float*)d_in[8];
    const float* Wpos_w  = (const float*)d_in[9];
    const float* Wpos_b  = (const float*)d_in[10];

    float* out      = (float*)d_out;
    float* out_seed = out;
    float* out_pos  = out + (size_t)NPTS * DM;
    float* out_cg   = out + (size_t)2 * NPTS * DM;

    cudaFuncSetAttribute(k_gemm, cudaFuncAttributeMaxDynamicSharedMemorySize, SMEM_G);
    cudaFuncSetAttribute(k_pegemm, cudaFuncAttributeMaxDynamicSharedMemorySize, SMEM_PE);

    k_prep<<<(PREP_N + 255) / 256, 256>>>(Wseed_w, Wpos_w);
    k_gemm<<<BATCH * TPB64, 256, SMEM_G>>>(L1, L2, L3, L4);
    k_pegemm<<<NPTS / 64, 256, SMEM_PE>>>(coords, Wpos_b, out_pos, out_cg);
    k_gather<<<dim3(KPTS / 8, BATCH), 256>>>(coords, Wseed_b, ln_g, ln_b, out_seed);
}

// round 8
// speedup vs baseline: 2.9053x; 1.0267x over previous
#include <cuda_runtime.h>
#include <cuda_fp16.h>
#include <cstdint>

// ---------------------------------------------------------------------------
// Problem constants
// ---------------------------------------------------------------------------
#define BATCH     8
#define KPTS      4096
#define NPTS      (BATCH * KPTS)      // 32768
#define DM        192
#define DIN       800
#define PEW       32
#define PIX_PB    21760               // 16384+4096+1024+256
#define TPB64     340                 // 64-px tiles per batch
#define NPE_BLK   (NPTS / 64)         // 512
#define NGEMM_BLK (BATCH * TPB64)     // 2720

__device__ __constant__ int c_HW[4]    = {16384, 4096, 1024, 256};
__device__ __constant__ int c_Wd[4]    = {128, 64, 32, 16};
__device__ __constant__ int c_LOFF[4]  = {0, 16384, 20480, 21504};

// ---------------------------------------------------------------------------
// Static device scratch
// ---------------------------------------------------------------------------
__device__ __half g_P[(size_t)BATCH * PIX_PB * DM];   // projected maps [pix][d] fp16
__device__ __half g_peW[(size_t)NPTS * DM];           // PE @ Wseed_pe^T  (fp16)
__device__ __half g_Wbf[4][DM][DM];                   // [level][d][c] fp16
__device__ __half g_Wbfpe[2][DM][PEW];                // [z][d][j]

// ---------------------------------------------------------------------------
// PTX helpers (generic sm_80+ — safe on compute_103 target)
// ---------------------------------------------------------------------------
__device__ __forceinline__ uint32_t smem_u32(const void* p) {
    uint32_t a;
    asm("{ .reg .u64 t; cvta.to.shared.u64 t, %1; cvt.u32.u64 %0, t; }" : "=r"(a) : "l"(p));
    return a;
}
__device__ __forceinline__ void ldmx4(uint32_t r[4], uint32_t addr) {
    asm volatile("ldmatrix.sync.aligned.m8n8.x4.shared.b16 {%0,%1,%2,%3}, [%4];"
                 : "=r"(r[0]), "=r"(r[1]), "=r"(r[2]), "=r"(r[3]) : "r"(addr));
}
__device__ __forceinline__ void mma_f16(float c[4], const uint32_t a[4],
                                        uint32_t b0, uint32_t b1) {
    asm volatile("mma.sync.aligned.m16n8k16.row.col.f32.f16.f16.f32 "
                 "{%0,%1,%2,%3}, {%4,%5,%6,%7}, {%8,%9}, {%0,%1,%2,%3};"
                 : "+f"(c[0]), "+f"(c[1]), "+f"(c[2]), "+f"(c[3])
                 : "r"(a[0]), "r"(a[1]), "r"(a[2]), "r"(a[3]), "r"(b0), "r"(b1));
}
#define CP_ASYNC16(dst, src) \
    asm volatile("cp.async.cg.shared.global [%0], [%1], 16;" \
                 :: "r"(dst), "l"(src) : "memory")
#define CP_COMMIT()  asm volatile("cp.async.commit_group;" ::: "memory")
#define CP_WAIT0()   asm volatile("cp.async.wait_group 0;" ::: "memory")

// ---------------------------------------------------------------------------
// Kernel 1: weight prep — fp16 weights
// ---------------------------------------------------------------------------
#define PREP_N (4 * DM * DM + 2 * DM * PEW)
__global__ void __launch_bounds__(256) k_prep(const float* __restrict__ Wseed_w,
                                              const float* __restrict__ Wpos_w) {
    int idx = blockIdx.x * 256 + threadIdx.x;
    if (idx < 4 * DM * DM) {
        int l = idx / (DM * DM);
        int d = (idx % (DM * DM)) / DM;
        int c = idx % DM;
        ((__half*)g_Wbf)[idx] = __float2half_rn(Wseed_w[(size_t)d * DIN + l * DM + c]);
    } else if (idx < PREP_N) {
        int i2 = idx - 4 * DM * DM;
        int z = i2 / (DM * PEW);
        int d = (i2 % (DM * PEW)) / PEW;
        int j = i2 % PEW;
        float w = z ? Wpos_w[(size_t)d * PEW + j] : Wseed_w[(size_t)d * DIN + 768 + j];
        g_Wbfpe[z][d][j] = __float2half_rn(w);
    }
}

// ---------------------------------------------------------------------------
// Fused main kernel (128 threads/block):
//   blocks [0, NPE_BLK):           PE + dual GEMM + center_grid
//   blocks [NPE_BLK, +NGEMM_BLK):  projection GEMM (64px x 192d per block)
// ---------------------------------------------------------------------------
// gemm-part smem layout
#define SM_BSH 0                      // Bs [192][72] half = 27648
#define SM_ASH 27648                  // As [64][72] half  = 9216
#define SM_FS0 36864                  // Fs x2 buffers fp32 [64][68]
#define FS_SZ  17408
#define SMEM_MAIN (SM_FS0 + 2 * FS_SZ)   // 71680
// pegemm-part smem layout (within same allocation)
#define PG_AS0 0                      // As [64][40] half = 5120
#define PG_BS(z) (5120 + (z) * 15360) // Bs [192][40] half x2
#define PG_CS  35840                  // coords (512B)

__device__ __forceinline__ void gemm_part(char* smem, int gb,
                                          const float* F0, const float* F1,
                                          const float* F2, const float* F3) {
    __half* As_h = (__half*)(smem + SM_ASH);
    const uint32_t u_base = smem_u32(smem);
    const uint32_t u_bsh = u_base + SM_BSH;
    const uint32_t u_ash = u_base + SM_ASH;
    const uint32_t u_fs0 = u_base + SM_FS0;

    const int tid = threadIdx.x;
    const int lane = tid & 31, wid = tid >> 5;
    const int warp_m = wid & 1, warp_n = wid >> 1;   // 2m x 2n, warp tile 32px x 96d

    const int b = gb / TPB64;
    const int r = gb % TPB64;
    int level, tin;
    if (r < 256)      { level = 0; tin = r; }
    else if (r < 320) { level = 1; tin = r - 256; }
    else if (r < 336) { level = 2; tin = r - 320; }
    else              { level = 3; tin = r - 336; }
    const int HW = c_HW[level];
    const float* F = (level == 0) ? F0 : (level == 1) ? F1 : (level == 2) ? F2 : F3;
    F += (size_t)b * DM * HW + tin * 64;
    const __half* Wh = &g_Wbf[level][0][0];

    float acc[2][12][4];
#pragma unroll
    for (int mi = 0; mi < 2; mi++)
#pragma unroll
        for (int n = 0; n < 12; n++)
#pragma unroll
            for (int e = 0; e < 4; e++) acc[mi][n][e] = 0.0f;

    const int arow = lane & 15;
    const int acol8 = (lane >> 4) << 3;
    const int brow = (lane & 7) + ((lane >> 4) << 3);
    const int bcol8 = ((lane >> 3) & 1) << 3;
    const int px_cv = tid >> 1;        // convert: pixel (0..63)
    const int q2 = tid & 1;            // convert: c-half (32 c's each)

    const int fc = tid >> 4, fp4 = (tid & 15) << 2;
#define ISSUE_F(c0, buf) do { \
        uint32_t fdst = u_fs0 + (buf) * FS_SZ + fp4 * 4; \
        const float* fsrc = F + (size_t)((c0) + fc) * HW + fp4; \
        _Pragma("unroll") \
        for (int rr = 0; rr < 8; rr++) \
            CP_ASYNC16(fdst + (fc + rr * 8) * 272, fsrc + (size_t)(rr * 8) * HW); \
    } while (0)
#define ISSUE_B(c0) do { \
        _Pragma("unroll") \
        for (int ii = tid; ii < 1536; ii += 128) { \
            int d = ii >> 3, u = ii & 7; \
            uint32_t off = (uint32_t)(d * 144 + u * 16); \
            CP_ASYNC16(u_bsh + off, Wh + d * DM + (c0) + u * 8); \
        } \
    } while (0)

    ISSUE_F(0, 0);
    ISSUE_B(0);
    CP_COMMIT();

    for (int cz = 0; cz < 3; cz++) {
        const int c0 = cz * 64;
        const int buf = cz & 1;
        CP_WAIT0();
        __syncthreads();
        if (cz < 2) { ISSUE_F(c0 + 64, buf ^ 1); CP_COMMIT(); }

        // convert Fs[buf] -> As fp16 (transpose c<->px); each thread 32 halves
        const float* Fsb = (const float*)(smem + SM_FS0 + buf * FS_SZ);
#pragma unroll
        for (int g = 0; g < 4; g++) {
            union { unsigned short s[8]; uint4 v; } uh;
#pragma unroll
            for (int e = 0; e < 8; e++) {
                int c = q2 * 32 + g * 8 + e;
                __half h = __float2half_rn(Fsb[c * 68 + px_cv]);
                uh.s[e] = *(unsigned short*)&h;
            }
            *(uint4*)(As_h + px_cv * 72 + q2 * 32 + g * 8) = uh.v;
        }
        __syncthreads();

#pragma unroll
        for (int ks = 0; ks < 4; ks++) {
            const int k0 = ks * 16;
            uint32_t ah[2][4];
#pragma unroll
            for (int mi = 0; mi < 2; mi++) {
                uint32_t off = (uint32_t)((warp_m * 32 + mi * 16 + arow) * 72 + k0 + acol8) * 2;
                ldmx4(ah[mi], u_ash + off);
            }
            uint32_t bh[6][4];
#pragma unroll
            for (int nj = 0; nj < 6; nj++) {
                uint32_t off = (uint32_t)((warp_n * 96 + nj * 16 + brow) * 72 + k0 + bcol8) * 2;
                ldmx4(bh[nj], u_bsh + off);
            }
#pragma unroll
            for (int mi = 0; mi < 2; mi++)
#pragma unroll
                for (int n = 0; n < 12; n++)
                    mma_f16(acc[mi][n], ah[mi], bh[n >> 1][(n & 1) * 2],
                            bh[n >> 1][(n & 1) * 2 + 1]);
        }
        __syncthreads();
        if (cz < 2) { ISSUE_B(c0 + 64); CP_COMMIT(); }
    }

    // epilogue: fp16 writes
    const size_t rowbase = (size_t)b * PIX_PB + c_LOFF[level] + tin * 64 + warp_m * 32;
    const int dbase = warp_n * 96 + (lane & 3) * 2;
    const int rsub = lane >> 2;
#pragma unroll
    for (int mi = 0; mi < 2; mi++) {
        size_t r0 = (rowbase + mi * 16 + rsub) * DM;
        size_t r1 = (rowbase + mi * 16 + rsub + 8) * DM;
#pragma unroll
        for (int n = 0; n < 12; n++) {
            int d = dbase + n * 8;
            *(__half2*)(g_P + r0 + d) = __floats2half2_rn(acc[mi][n][0], acc[mi][n][1]);
            *(__half2*)(g_P + r1 + d) = __floats2half2_rn(acc[mi][n][2], acc[mi][n][3]);
        }
    }
}

__device__ __forceinline__ void pe_part(char* smem, int pb,
                                        const float* __restrict__ coords,
                                        const float* __restrict__ Wpos_b,
                                        float* __restrict__ out_pos,
                                        float* __restrict__ out_cg) {
    __half* As0 = (__half*)(smem + PG_AS0);
    float* cs = (float*)(smem + PG_CS);
    const uint32_t u_base = smem_u32(smem);

    const int p0 = pb * 64;
    const int tid = threadIdx.x;
    const int lane = tid & 31, wid = tid >> 5;
    const int warp_m = wid & 1, warp_n = wid >> 1;

    cs[tid] = coords[(size_t)p0 * 2 + tid];
#pragma unroll
    for (int i = tid; i < 768; i += 128) {
        int d = i >> 2, u = i & 3;
#pragma unroll
        for (int z = 0; z < 2; z++)
            *(uint4*)(smem + PG_BS(z) + (d * 40 + u * 8) * 2) =
                *(const uint4*)(&g_Wbfpe[z][d][0] + u * 8);
    }
    __syncthreads();

#pragma unroll
    for (int i = tid; i < 1024; i += 128) {
        int p = i >> 4, k = i & 15;
        int s = k >> 3, fq = k & 7;
        float c = cs[p * 2 + s];
        float arg = c * (1.0f / 512.0f) * (float)(1 << fq) * 6.283185307179586f;
        float sv, cv;
        sincosf(arg, &sv, &cv);
        int js = s * 16 + fq, jc = js + 8;
        As0[p * 40 + js] = __float2half_rn(sv);
        As0[p * 40 + jc] = __float2half_rn(cv);
    }
    if (tid < 64) {
        int gp = p0 + tid;
        out_cg[(size_t)gp * 2 + 0] = 2.0f * cs[tid * 2 + 0] / 511.0f - 1.0f;
        out_cg[(size_t)gp * 2 + 1] = 2.0f * cs[tid * 2 + 1] / 511.0f - 1.0f;
    }
    __syncthreads();

    const int arow = lane & 15;
    const int acol8 = (lane >> 4) << 3;
    const int brow = (lane & 7) + ((lane >> 4) << 3);
    const int bcol8 = ((lane >> 3) & 1) << 3;

    uint32_t ah[2][2][4];   // [ks][mi]
#pragma unroll
    for (int ks = 0; ks < 2; ks++)
#pragma unroll
        for (int mi = 0; mi < 2; mi++) {
            uint32_t off = (uint32_t)((warp_m * 32 + mi * 16 + arow) * 40 + ks * 16 + acol8) * 2;
            ldmx4(ah[ks][mi], u_base + PG_AS0 + off);
        }

    const int dbase = warp_n * 96 + (lane & 3) * 2;
    const int rsub = lane >> 2;

#pragma unroll
    for (int z = 0; z < 2; z++) {
        float acc[2][12][4];
#pragma unroll
        for (int mi = 0; mi < 2; mi++)
#pragma unroll
            for (int n = 0; n < 12; n++)
#pragma unroll
                for (int e = 0; e < 4; e++) acc[mi][n][e] = 0.0f;

#pragma unroll
        for (int ks = 0; ks < 2; ks++) {
            uint32_t bh[6][4];
#pragma unroll
            for (int nj = 0; nj < 6; nj++) {
                uint32_t off = (uint32_t)((warp_n * 96 + nj * 16 + brow) * 40 + ks * 16 + bcol8) * 2;
                ldmx4(bh[nj], u_base + PG_BS(z) + off);
            }
#pragma unroll
            for (int mi = 0; mi < 2; mi++)
#pragma unroll
                for (int n = 0; n < 12; n++)
                    mma_f16(acc[mi][n], ah[ks][mi], bh[n >> 1][(n & 1) * 2],
                            bh[n >> 1][(n & 1) * 2 + 1]);
        }

        const size_t rowbase = (size_t)p0 + warp_m * 32;
#pragma unroll
        for (int mi = 0; mi < 2; mi++) {
            size_t r0 = (rowbase + mi * 16 + rsub) * DM;
            size_t r1 = (rowbase + mi * 16 + rsub + 8) * DM;
#pragma unroll
            for (int n = 0; n < 12; n++) {
                int d = dbase + n * 8;
                if (z == 0) {
                    *(__half2*)(g_peW + r0 + d) = __floats2half2_rn(acc[mi][n][0], acc[mi][n][1]);
                    *(__half2*)(g_peW + r1 + d) = __floats2half2_rn(acc[mi][n][2], acc[mi][n][3]);
                } else {
                    float b0 = __ldg(Wpos_b + d), b1 = __ldg(Wpos_b + d + 1);
                    *(float2*)(out_pos + r0 + d) = make_float2(acc[mi][n][0] + b0,
                                                               acc[mi][n][1] + b1);
                    *(float2*)(out_pos + r1 + d) = make_float2(acc[mi][n][2] + b0,
                                                               acc[mi][n][3] + b1);
                }
            }
        }
    }
}

__global__ void __launch_bounds__(128, 2) k_main(const float* __restrict__ F0,
                                                 const float* __restrict__ F1,
                                                 const float* __restrict__ F2,
                                                 const float* __restrict__ F3,
                                                 const float* __restrict__ coords,
                                                 const float* __restrict__ Wpos_b,
                                                 float* __restrict__ out_pos,
                                                 float* __restrict__ out_cg) {
    extern __shared__ char smem[];
    if (blockIdx.x < NPE_BLK)
        pe_part(smem, blockIdx.x, coords, Wpos_b, out_pos, out_cg);
    else
        gemm_part(smem, blockIdx.x - NPE_BLK, F0, F1, F2, F3);
}

// ---------------------------------------------------------------------------
// Kernel 3: gather + bilinear + LayerNorm (1 warp = 1 point, fp16 g_P/g_peW)
// ---------------------------------------------------------------------------
__global__ void __launch_bounds__(256) k_gather(const float* __restrict__ coords,
                                                const float* __restrict__ seed_b,
                                                const float* __restrict__ lng,
                                                const float* __restrict__ lnb,
                                                float* __restrict__ out_seed) {
    const int b = blockIdx.y;
    const int wid = threadIdx.x >> 5;
    const int lane = threadIdx.x & 31;
    const int k = blockIdx.x * 8 + wid;
    const int gp = b * KPTS + k;
    const int l4 = lane * 4;
    const int l2 = 128 + lane * 2;

    const float cx = coords[(size_t)gp * 2 + 0];
    const float cy = coords[(size_t)gp * 2 + 1];
    const float gx = 2.0f * cx / 511.0f - 1.0f;
    const float gy = 2.0f * cy / 511.0f - 1.0f;

    const __half* peW = g_peW + (size_t)gp * DM;
    float4 a4;
    float2 a2;
    {
        float4 s4 = __ldg((const float4*)(seed_b + l4));
        uint2 praw = __ldg((const uint2*)(peW + l4));
        float2 p01 = __half22float2(*(const __half2*)&praw.x);
        float2 p23 = __half22float2(*(const __half2*)&praw.y);
        a4 = make_float4(s4.x + p01.x, s4.y + p01.y, s4.z + p23.x, s4.w + p23.y);
        float2 s2 = __ldg((const float2*)(seed_b + l2));
        uint32_t praw2 = __ldg((const uint32_t*)(peW + l2));
        float2 p45 = __half22float2(*(const __half2*)&praw2);
        a2 = make_float2(s2.x + p45.x, s2.y + p45.y);
    }

#pragma unroll
    for (int l = 0; l < 4; l++) {
        const int W = c_Wd[l];
        const float ix = (gx + 1.0f) * 0.5f * (float)(W - 1);
        const float iy = (gy + 1.0f) * 0.5f * (float)(W - 1);
        const float fx0 = floorf(ix);
        const float fy0 = floorf(iy);
        const float wx = ix - fx0;
        const float wy = iy - fy0;
        int x0 = min(max((int)fx0, 0), W - 1);
        int x1 = min(max((int)fx0 + 1, 0), W - 1);
        int y0 = min(max((int)fy0, 0), W - 1);
        int y1 = min(max((int)fy0 + 1, 0), W - 1);
        const size_t base = ((size_t)b * PIX_PB + c_LOFF[l]) * DM;
        const __half* cp[4] = {g_P + base + (size_t)(y0 * W + x0) * DM,
                               g_P + base + (size_t)(y0 * W + x1) * DM,
                               g_P + base + (size_t)(y1 * W + x0) * DM,
                               g_P + base + (size_t)(y1 * W + x1) * DM};
        const float ww[4] = {(1.0f - wx) * (1.0f - wy), wx * (1.0f - wy),
                             (1.0f - wx) * wy, wx * wy};
#pragma unroll
        for (int c = 0; c < 4; c++) {
            uint2 raw = __ldg((const uint2*)(cp[c] + l4));
            float2 f01 = __half22float2(*(const __half2*)&raw.x);
            float2 f23 = __half22float2(*(const __half2*)&raw.y);
            uint32_t raw2 = __ldg((const uint32_t*)(cp[c] + l2));
            float2 f45 = __half22float2(*(const __half2*)&raw2);
            a4.x += ww[c] * f01.x; a4.y += ww[c] * f01.y;
            a4.z += ww[c] * f23.x; a4.w += ww[c] * f23.y;
            a2.x += ww[c] * f45.x; a2.y += ww[c] * f45.y;
        }
    }

    float s = a4.x + a4.y + a4.z + a4.w + a2.x + a2.y;
    float s2 = a4.x * a4.x + a4.y * a4.y + a4.z * a4.z + a4.w * a4.w
             + a2.x * a2.x + a2.y * a2.y;
#pragma unroll
    for (int o = 16; o > 0; o >>= 1) {
        s  += __shfl_xor_sync(0xFFFFFFFFu, s, o);
        s2 += __shfl_xor_sync(0xFFFFFFFFu, s2, o);
    }
    const float mu = s * (1.0f / 192.0f);
    const float var = s2 * (1.0f / 192.0f) - mu * mu;
    const float inv = rsqrtf(var + 1e-5f);

    float* dst = out_seed + (size_t)gp * DM;
    {
        float4 g4 = __ldg((const float4*)(lng + l4));
        float4 b4 = __ldg((const float4*)(lnb + l4));
        float4 o4 = make_float4((a4.x - mu) * inv * g4.x + b4.x,
                                (a4.y - mu) * inv * g4.y + b4.y,
                                (a4.z - mu) * inv * g4.z + b4.z,
                                (a4.w - mu) * inv * g4.w + b4.w);
        *(float4*)(dst + l4) = o4;
        float2 g2 = __ldg((const float2*)(lng + l2));
        float2 b2 = __ldg((const float2*)(lnb + l2));
        *(float2*)(dst + l2) = make_float2((a2.x - mu) * inv * g2.x + b2.x,
                                           (a2.y - mu) * inv * g2.y + b2.y);
    }
}

// ---------------------------------------------------------------------------
// launch
// ---------------------------------------------------------------------------
extern "C" void kernel_launch(void* const* d_in, const int* in_sizes, int n_in,
                              void* d_out, int out_size) {
    const float* coords  = (const float*)d_in[0];
    const float* L1      = (const float*)d_in[1];
    const float* L2      = (const float*)d_in[2];
    const float* L3      = (const float*)d_in[3];
    const float* L4      = (const float*)d_in[4];
    const float* Wseed_w = (const float*)d_in[5];
    const float* Wseed_b = (const float*)d_in[6];
    const float* ln_g    = (const float*)d_in[7];
    const float* ln_b    = (const float*)d_in[8];
    const float* Wpos_w  = (const float*)d_in[9];
    const float* Wpos_b  = (const float*)d_in[10];

    float* out      = (float*)d_out;
    float* out_seed = out;
    float* out_pos  = out + (size_t)NPTS * DM;
    float* out_cg   = out + (size_t)2 * NPTS * DM;

    cudaFuncSetAttribute(k_main, cudaFuncAttributeMaxDynamicSharedMemorySize, SMEM_MAIN);

    k_prep<<<(PREP_N + 255) / 256, 256>>>(Wseed_w, Wpos_w);
    k_main<<<NPE_BLK + NGEMM_BLK, 128, SMEM_MAIN>>>(L1, L2, L3, L4,
                                                    coords, Wpos_b, out_pos, out_cg);
    k_gather<<<dim3(KPTS / 8, BATCH), 256>>>(coords, Wseed_b, ln_g, ln_b, out_seed);
}

// round 9
// speedup vs baseline: 3.1829x; 1.0956x over previous
#include <cuda_runtime.h>
#include <cuda_fp16.h>
#include <cstdint>

// ---------------------------------------------------------------------------
// Problem constants
// ---------------------------------------------------------------------------
#define BATCH     8
#define KPTS      4096
#define NPTS      (BATCH * KPTS)      // 32768
#define DM        192
#define DIN       800
#define PEW       32
#define PIX_PB    21760               // 16384+4096+1024+256
#define TPB64     340                 // 64-px tiles per batch
#define NPE_BLK   (NPTS / 64)         // 512
#define NGEMM_BLK (BATCH * TPB64)     // 2720

__device__ __constant__ int c_HW[4]    = {16384, 4096, 1024, 256};
__device__ __constant__ int c_Wd[4]    = {128, 64, 32, 16};
__device__ __constant__ int c_LOFF[4]  = {0, 16384, 20480, 21504};

// ---------------------------------------------------------------------------
// Static device scratch
// ---------------------------------------------------------------------------
__device__ __half g_P[(size_t)BATCH * PIX_PB * DM];   // projected maps [pix][d] fp16
__device__ __half g_peW[(size_t)NPTS * DM];           // PE @ Wseed_pe^T  (fp16)
__device__ __half g_Wbf[4][DM][DM];                   // [level][d][c] fp16
__device__ __half g_Wbfpe[2][DM][PEW];                // [z][d][j]

// ---------------------------------------------------------------------------
// PTX helpers (generic sm_80+ — safe on compute_103 target)
// ---------------------------------------------------------------------------
__device__ __forceinline__ uint32_t smem_u32(const void* p) {
    uint32_t a;
    asm("{ .reg .u64 t; cvta.to.shared.u64 t, %1; cvt.u32.u64 %0, t; }" : "=r"(a) : "l"(p));
    return a;
}
__device__ __forceinline__ void ldmx4(uint32_t r[4], uint32_t addr) {
    asm volatile("ldmatrix.sync.aligned.m8n8.x4.shared.b16 {%0,%1,%2,%3}, [%4];"
                 : "=r"(r[0]), "=r"(r[1]), "=r"(r[2]), "=r"(r[3]) : "r"(addr));
}
__device__ __forceinline__ void mma_f16(float c[4], const uint32_t a[4],
                                        uint32_t b0, uint32_t b1) {
    asm volatile("mma.sync.aligned.m16n8k16.row.col.f32.f16.f16.f32 "
                 "{%0,%1,%2,%3}, {%4,%5,%6,%7}, {%8,%9}, {%0,%1,%2,%3};"
                 : "+f"(c[0]), "+f"(c[1]), "+f"(c[2]), "+f"(c[3])
                 : "r"(a[0]), "r"(a[1]), "r"(a[2]), "r"(a[3]), "r"(b0), "r"(b1));
}
#define CP_ASYNC16(dst, src) \
    asm volatile("cp.async.cg.shared.global [%0], [%1], 16;" \
                 :: "r"(dst), "l"(src) : "memory")
#define CP_COMMIT()  asm volatile("cp.async.commit_group;" ::: "memory")
#define CP_WAIT0()   asm volatile("cp.async.wait_group 0;" ::: "memory")

// ---------------------------------------------------------------------------
// Kernel 1: weight prep — fp16 weights (float4-vectorized)
// ---------------------------------------------------------------------------
#define PREP_N ((4 * DM * DM + 2 * DM * PEW) / 4)
__global__ void __launch_bounds__(256) k_prep(const float* __restrict__ Wseed_w,
                                              const float* __restrict__ Wpos_w) {
    int idx = blockIdx.x * 256 + threadIdx.x;
    if (idx < DM * DM) {           // 4 levels x (DM*DM/4) quads
        int l = (idx * 4) / (DM * DM);
        int rem = (idx * 4) % (DM * DM);
        int d = rem / DM, c = rem % DM;
        float4 w = *(const float4*)(Wseed_w + (size_t)d * DIN + l * DM + c);
        __half* dst = &g_Wbf[l][d][c];
        dst[0] = __float2half_rn(w.x); dst[1] = __float2half_rn(w.y);
        dst[2] = __float2half_rn(w.z); dst[3] = __float2half_rn(w.w);
    } else if (idx < PREP_N) {
        int i2 = (idx - DM * DM) * 4;
        int z = i2 / (DM * PEW);
        int rem = i2 % (DM * PEW);
        int d = rem / PEW, j = rem % PEW;
        const float* src = z ? (Wpos_w + (size_t)d * PEW + j)
                             : (Wseed_w + (size_t)d * DIN + 768 + j);
        float4 w = *(const float4*)src;
        __half* dst = &g_Wbfpe[z][d][j];
        dst[0] = __float2half_rn(w.x); dst[1] = __float2half_rn(w.y);
        dst[2] = __float2half_rn(w.z); dst[3] = __float2half_rn(w.w);
    }
}

// ---------------------------------------------------------------------------
// Fused main kernel (128 threads/block):
//   blocks [0, NGEMM_BLK):          projection GEMM (64px x 192d per block)
//   blocks [NGEMM_BLK, +NPE_BLK):   PE + dual GEMM + center_grid
// ---------------------------------------------------------------------------
#define SM_BSH 0                      // Bs [192][72] half = 27648
#define SM_ASH 27648                  // As [64][72] half  = 9216
#define SM_FS0 36864                  // Fs x2 buffers fp32 [64][68]
#define FS_SZ  17408
#define SMEM_MAIN (SM_FS0 + 2 * FS_SZ)   // 71680
// pegemm-part smem layout (within same allocation)
#define PG_AS0 0                      // As [64][40] half = 5120
#define PG_BS(z) (5120 + (z) * 15360) // Bs [192][40] half x2
#define PG_CS  35840                  // coords (512B)

__device__ __forceinline__ void gemm_part(char* smem, int gb,
                                          const float* F0, const float* F1,
                                          const float* F2, const float* F3) {
    __half* As_h = (__half*)(smem + SM_ASH);
    const uint32_t u_base = smem_u32(smem);
    const uint32_t u_bsh = u_base + SM_BSH;
    const uint32_t u_ash = u_base + SM_ASH;
    const uint32_t u_fs0 = u_base + SM_FS0;

    const int tid = threadIdx.x;
    const int lane = tid & 31, wid = tid >> 5;
    const int warp_m = wid & 1, warp_n = wid >> 1;   // 2m x 2n, warp tile 32px x 96d

    const int b = gb / TPB64;
    const int r = gb % TPB64;
    int level, tin;
    if (r < 256)      { level = 0; tin = r; }
    else if (r < 320) { level = 1; tin = r - 256; }
    else if (r < 336) { level = 2; tin = r - 320; }
    else              { level = 3; tin = r - 336; }
    const int HW = c_HW[level];
    const float* F = (level == 0) ? F0 : (level == 1) ? F1 : (level == 2) ? F2 : F3;
    F += (size_t)b * DM * HW + tin * 64;
    const __half* Wh = &g_Wbf[level][0][0];

    float acc[2][12][4];
#pragma unroll
    for (int mi = 0; mi < 2; mi++)
#pragma unroll
        for (int n = 0; n < 12; n++)
#pragma unroll
            for (int e = 0; e < 4; e++) acc[mi][n][e] = 0.0f;

    const int arow = lane & 15;
    const int acol8 = (lane >> 4) << 3;
    const int brow = (lane & 7) + ((lane >> 4) << 3);
    const int bcol8 = ((lane >> 3) & 1) << 3;
    const int px_cv = tid >> 1;
    const int q2 = tid & 1;

    const int fc = tid >> 4, fp4 = (tid & 15) << 2;
#define ISSUE_F(c0, buf) do { \
        uint32_t fdst = u_fs0 + (buf) * FS_SZ + fp4 * 4; \
        const float* fsrc = F + (size_t)((c0) + fc) * HW + fp4; \
        _Pragma("unroll") \
        for (int rr = 0; rr < 8; rr++) \
            CP_ASYNC16(fdst + (fc + rr * 8) * 272, fsrc + (size_t)(rr * 8) * HW); \
    } while (0)
#define ISSUE_B(c0) do { \
        _Pragma("unroll") \
        for (int ii = tid; ii < 1536; ii += 128) { \
            int d = ii >> 3, u = ii & 7; \
            uint32_t off = (uint32_t)(d * 144 + u * 16); \
            CP_ASYNC16(u_bsh + off, Wh + d * DM + (c0) + u * 8); \
        } \
    } while (0)

    ISSUE_F(0, 0);
    ISSUE_B(0);
    CP_COMMIT();

    for (int cz = 0; cz < 3; cz++) {
        const int c0 = cz * 64;
        const int buf = cz & 1;
        CP_WAIT0();
        __syncthreads();
        if (cz < 2) { ISSUE_F(c0 + 64, buf ^ 1); CP_COMMIT(); }

        // convert Fs[buf] -> As fp16 (transpose c<->px); each thread 32 halves
        const float* Fsb = (const float*)(smem + SM_FS0 + buf * FS_SZ);
#pragma unroll
        for (int g = 0; g < 4; g++) {
            union { unsigned short s[8]; uint4 v; } uh;
#pragma unroll
            for (int e = 0; e < 8; e++) {
                int c = q2 * 32 + g * 8 + e;
                __half h = __float2half_rn(Fsb[c * 68 + px_cv]);
                uh.s[e] = *(unsigned short*)&h;
            }
            *(uint4*)(As_h + px_cv * 72 + q2 * 32 + g * 8) = uh.v;
        }
        __syncthreads();

#pragma unroll
        for (int ks = 0; ks < 4; ks++) {
            const int k0 = ks * 16;
            uint32_t ah[2][4];
#pragma unroll
            for (int mi = 0; mi < 2; mi++) {
                uint32_t off = (uint32_t)((warp_m * 32 + mi * 16 + arow) * 72 + k0 + acol8) * 2;
                ldmx4(ah[mi], u_ash + off);
            }
            uint32_t bh[6][4];
#pragma unroll
            for (int nj = 0; nj < 6; nj++) {
                uint32_t off = (uint32_t)((warp_n * 96 + nj * 16 + brow) * 72 + k0 + bcol8) * 2;
                ldmx4(bh[nj], u_bsh + off);
            }
#pragma unroll
            for (int mi = 0; mi < 2; mi++)
#pragma unroll
                for (int n = 0; n < 12; n++)
                    mma_f16(acc[mi][n], ah[mi], bh[n >> 1][(n & 1) * 2],
                            bh[n >> 1][(n & 1) * 2 + 1]);
        }
        __syncthreads();
        if (cz < 2) { ISSUE_B(c0 + 64); CP_COMMIT(); }
    }

    // epilogue: fp16 writes
    const size_t rowbase = (size_t)b * PIX_PB + c_LOFF[level] + tin * 64 + warp_m * 32;
    const int dbase = warp_n * 96 + (lane & 3) * 2;
    const int rsub = lane >> 2;
#pragma unroll
    for (int mi = 0; mi < 2; mi++) {
        size_t r0 = (rowbase + mi * 16 + rsub) * DM;
        size_t r1 = (rowbase + mi * 16 + rsub + 8) * DM;
#pragma unroll
        for (int n = 0; n < 12; n++) {
            int d = dbase + n * 8;
            *(__half2*)(g_P + r0 + d) = __floats2half2_rn(acc[mi][n][0], acc[mi][n][1]);
            *(__half2*)(g_P + r1 + d) = __floats2half2_rn(acc[mi][n][2], acc[mi][n][3]);
        }
    }
}

__device__ __forceinline__ void pe_part(char* smem, int pb,
                                        const float* __restrict__ coords,
                                        const float* __restrict__ Wpos_b,
                                        float* __restrict__ out_pos,
                                        float* __restrict__ out_cg) {
    __half* As0 = (__half*)(smem + PG_AS0);
    float* cs = (float*)(smem + PG_CS);
    const uint32_t u_base = smem_u32(smem);

    const int p0 = pb * 64;
    const int tid = threadIdx.x;
    const int lane = tid & 31, wid = tid >> 5;
    const int warp_m = wid & 1, warp_n = wid >> 1;

    cs[tid] = coords[(size_t)p0 * 2 + tid];
#pragma unroll
    for (int i = tid; i < 768; i += 128) {
        int d = i >> 2, u = i & 3;
#pragma unroll
        for (int z = 0; z < 2; z++)
            *(uint4*)(smem + PG_BS(z) + (d * 40 + u * 8) * 2) =
                *(const uint4*)(&g_Wbfpe[z][d][0] + u * 8);
    }
    __syncthreads();

#pragma unroll
    for (int i = tid; i < 1024; i += 128) {
        int p = i >> 4, k = i & 15;
        int s = k >> 3, fq = k & 7;
        float c = cs[p * 2 + s];
        float arg = c * (1.0f / 512.0f) * (float)(1 << fq) * 6.283185307179586f;
        float sv, cv;
        sincosf(arg, &sv, &cv);
        int js = s * 16 + fq, jc = js + 8;
        As0[p * 40 + js] = __float2half_rn(sv);
        As0[p * 40 + jc] = __float2half_rn(cv);
    }
    if (tid < 64) {
        int gp = p0 + tid;
        out_cg[(size_t)gp * 2 + 0] = 2.0f * cs[tid * 2 + 0] / 511.0f - 1.0f;
        out_cg[(size_t)gp * 2 + 1] = 2.0f * cs[tid * 2 + 1] / 511.0f - 1.0f;
    }
    __syncthreads();

    const int arow = lane & 15;
    const int acol8 = (lane >> 4) << 3;
    const int brow = (lane & 7) + ((lane >> 4) << 3);
    const int bcol8 = ((lane >> 3) & 1) << 3;

    uint32_t ah[2][2][4];   // [ks][mi]
#pragma unroll
    for (int ks = 0; ks < 2; ks++)
#pragma unroll
        for (int mi = 0; mi < 2; mi++) {
            uint32_t off = (uint32_t)((warp_m * 32 + mi * 16 + arow) * 40 + ks * 16 + acol8) * 2;
            ldmx4(ah[ks][mi], u_base + PG_AS0 + off);
        }

    const int dbase = warp_n * 96 + (lane & 3) * 2;
    const int rsub = lane >> 2;

#pragma unroll
    for (int z = 0; z < 2; z++) {
        float acc[2][12][4];
#pragma unroll
        for (int mi = 0; mi < 2; mi++)
#pragma unroll
            for (int n = 0; n < 12; n++)
#pragma unroll
                for (int e = 0; e < 4; e++) acc[mi][n][e] = 0.0f;

#pragma unroll
        for (int ks = 0; ks < 2; ks++) {
            uint32_t bh[6][4];
#pragma unroll
            for (int nj = 0; nj < 6; nj++) {
                uint32_t off = (uint32_t)((warp_n * 96 + nj * 16 + brow) * 40 + ks * 16 + bcol8) * 2;
                ldmx4(bh[nj], u_base + PG_BS(z) + off);
            }
#pragma unroll
            for (int mi = 0; mi < 2; mi++)
#pragma unroll
                for (int n = 0; n < 12; n++)
                    mma_f16(acc[mi][n], ah[ks][mi], bh[n >> 1][(n & 1) * 2],
                            bh[n >> 1][(n & 1) * 2 + 1]);
        }

        const size_t rowbase = (size_t)p0 + warp_m * 32;
#pragma unroll
        for (int mi = 0; mi < 2; mi++) {
            size_t r0 = (rowbase + mi * 16 + rsub) * DM;
            size_t r1 = (rowbase + mi * 16 + rsub + 8) * DM;
#pragma unroll
            for (int n = 0; n < 12; n++) {
                int d = dbase + n * 8;
                if (z == 0) {
                    *(__half2*)(g_peW + r0 + d) = __floats2half2_rn(acc[mi][n][0], acc[mi][n][1]);
                    *(__half2*)(g_peW + r1 + d) = __floats2half2_rn(acc[mi][n][2], acc[mi][n][3]);
                } else {
                    float b0 = __ldg(Wpos_b + d), b1 = __ldg(Wpos_b + d + 1);
                    *(float2*)(out_pos + r0 + d) = make_float2(acc[mi][n][0] + b0,
                                                               acc[mi][n][1] + b1);
                    *(float2*)(out_pos + r1 + d) = make_float2(acc[mi][n][2] + b0,
                                                               acc[mi][n][3] + b1);
                }
            }
        }
    }
}

__global__ void __launch_bounds__(128, 3) k_main(const float* __restrict__ F0,
                                                 const float* __restrict__ F1,
                                                 const float* __restrict__ F2,
                                                 const float* __restrict__ F3,
                                                 const float* __restrict__ coords,
                                                 const float* __restrict__ Wpos_b,
                                                 float* __restrict__ out_pos,
                                                 float* __restrict__ out_cg) {
    extern __shared__ char smem[];
    if (blockIdx.x < NGEMM_BLK)
        gemm_part(smem, blockIdx.x, F0, F1, F2, F3);
    else
        pe_part(smem, blockIdx.x - NGEMM_BLK, coords, Wpos_b, out_pos, out_cg);
}

// ---------------------------------------------------------------------------
// Kernel 3: gather + bilinear + LayerNorm (1 warp = 1 point, fp16 g_P/g_peW)
// ---------------------------------------------------------------------------
__global__ void __launch_bounds__(256) k_gather(const float* __restrict__ coords,
                                                const float* __restrict__ seed_b,
                                                const float* __restrict__ lng,
                                                const float* __restrict__ lnb,
                                                float* __restrict__ out_seed) {
    const int b = blockIdx.y;
    const int wid = threadIdx.x >> 5;
    const int lane = threadIdx.x & 31;
    const int k = blockIdx.x * 8 + wid;
    const int gp = b * KPTS + k;
    const int l4 = lane * 4;
    const int l2 = 128 + lane * 2;

    const float cx = coords[(size_t)gp * 2 + 0];
    const float cy = coords[(size_t)gp * 2 + 1];
    const float gx = 2.0f * cx / 511.0f - 1.0f;
    const float gy = 2.0f * cy / 511.0f - 1.0f;

    const __half* peW = g_peW + (size_t)gp * DM;
    float4 a4;
    float2 a2;
    {
        float4 s4 = __ldg((const float4*)(seed_b + l4));
        uint2 praw = __ldg((const uint2*)(peW + l4));
        float2 p01 = __half22float2(*(const __half2*)&praw.x);
        float2 p23 = __half22float2(*(const __half2*)&praw.y);
        a4 = make_float4(s4.x + p01.x, s4.y + p01.y, s4.z + p23.x, s4.w + p23.y);
        float2 s2 = __ldg((const float2*)(seed_b + l2));
        uint32_t praw2 = __ldg((const uint32_t*)(peW + l2));
        float2 p45 = __half22float2(*(const __half2*)&praw2);
        a2 = make_float2(s2.x + p45.x, s2.y + p45.y);
    }

#pragma unroll
    for (int l = 0; l < 4; l++) {
        const int W = c_Wd[l];
        const float ix = (gx + 1.0f) * 0.5f * (float)(W - 1);
        const float iy = (gy + 1.0f) * 0.5f * (float)(W - 1);
        const float fx0 = floorf(ix);
        const float fy0 = floorf(iy);
        const float wx = ix - fx0;
        const float wy = iy - fy0;
        int x0 = min(max((int)fx0, 0), W - 1);
        int x1 = min(max((int)fx0 + 1, 0), W - 1);
        int y0 = min(max((int)fy0, 0), W - 1);
        int y1 = min(max((int)fy0 + 1, 0), W - 1);
        const size_t base = ((size_t)b * PIX_PB + c_LOFF[l]) * DM;
        const __half* cp[4] = {g_P + base + (size_t)(y0 * W + x0) * DM,
                               g_P + base + (size_t)(y0 * W + x1) * DM,
                               g_P + base + (size_t)(y1 * W + x0) * DM,
                               g_P + base + (size_t)(y1 * W + x1) * DM};
        const float ww[4] = {(1.0f - wx) * (1.0f - wy), wx * (1.0f - wy),
                             (1.0f - wx) * wy, wx * wy};
#pragma unroll
        for (int c = 0; c < 4; c++) {
            uint2 raw = __ldg((const uint2*)(cp[c] + l4));
            float2 f01 = __half22float2(*(const __half2*)&raw.x);
            float2 f23 = __half22float2(*(const __half2*)&raw.y);
            uint32_t raw2 = __ldg((const uint32_t*)(cp[c] + l2));
            float2 f45 = __half22float2(*(const __half2*)&raw2);
            a4.x += ww[c] * f01.x; a4.y += ww[c] * f01.y;
            a4.z += ww[c] * f23.x; a4.w += ww[c] * f23.y;
            a2.x += ww[c] * f45.x; a2.y += ww[c] * f45.y;
        }
    }

    float s = a4.x + a4.y + a4.z + a4.w + a2.x + a2.y;
    float s2 = a4.x * a4.x + a4.y * a4.y + a4.z * a4.z + a4.w * a4.w
             + a2.x * a2.x + a2.y * a2.y;
#pragma unroll
    for (int o = 16; o > 0; o >>= 1) {
        s  += __shfl_xor_sync(0xFFFFFFFFu, s, o);
        s2 += __shfl_xor_sync(0xFFFFFFFFu, s2, o);
    }
    const float mu = s * (1.0f / 192.0f);
    const float var = s2 * (1.0f / 192.0f) - mu * mu;
    const float inv = rsqrtf(var + 1e-5f);

    float* dst = out_seed + (size_t)gp * DM;
    {
        float4 g4 = __ldg((const float4*)(lng + l4));
        float4 b4 = __ldg((const float4*)(lnb + l4));
        float4 o4 = make_float4((a4.x - mu) * inv * g4.x + b4.x,
                                (a4.y - mu) * inv * g4.y + b4.y,
                                (a4.z - mu) * inv * g4.z + b4.z,
                                (a4.w - mu) * inv * g4.w + b4.w);
        *(float4*)(dst + l4) = o4;
        float2 g2 = __ldg((const float2*)(lng + l2));
        float2 b2 = __ldg((const float2*)(lnb + l2));
        *(float2*)(dst + l2) = make_float2((a2.x - mu) * inv * g2.x + b2.x,
                                           (a2.y - mu) * inv * g2.y + b2.y);
    }
}

// ---------------------------------------------------------------------------
// launch
// ---------------------------------------------------------------------------
extern "C" void kernel_launch(void* const* d_in, const int* in_sizes, int n_in,
                              void* d_out, int out_size) {
    const float* coords  = (const float*)d_in[0];
    const float* L1      = (const float*)d_in[1];
    const float* L2      = (const float*)d_in[2];
    const float* L3      = (const float*)d_in[3];
    const float* L4      = (const float*)d_in[4];
    const float* Wseed_w = (const float*)d_in[5];
    const float* Wseed_b = (const float*)d_in[6];
    const float* ln_g    = (const float*)d_in[7];
    const float* ln_b    = (const float*)d_in[8];
    const float* Wpos_w  = (const float*)d_in[9];
    const float* Wpos_b  = (const float*)d_in[10];

    float* out      = (float*)d_out;
    float* out_seed = out;
    float* out_pos  = out + (size_t)NPTS * DM;
    float* out_cg   = out + (size_t)2 * NPTS * DM;

    cudaFuncSetAttribute(k_main, cudaFuncAttributeMaxDynamicSharedMemorySize, SMEM_MAIN);

    k_prep<<<(PREP_N + 255) / 256, 256>>>(Wseed_w, Wpos_w);
    k_main<<<NGEMM_BLK + NPE_BLK, 128, SMEM_MAIN>>>(L1, L2, L3, L4,
                                                    coords, Wpos_b, out_pos, out_cg);
    k_gather<<<dim3(KPTS / 8, BATCH), 256>>>(coords, Wseed_b, ln_g, ln_b, out_seed);
}